// round 4
// baseline (speedup 1.0000x reference)
#include <cuda_runtime.h>
#include <cuda_bf16.h>

typedef unsigned long long u64;

#define SEQL   512
#define BATCH  32
#define HDIM   1024
#define VOCAB  8192
#define ML     (BATCH*SEQL)              /* 16384 */
#define LOGITS_ELEMS 134217728           /* 32*512*8192 */

// ---------------- scratch (cudaMalloc forbidden) ----------------
__device__ float g_pre[ML*HDIM];         // 64 MB, layout [t][b][h]
__device__ float g_hout[ML*HDIM];        // 64 MB, layout [t][b][h]
__device__ int   g_map1[ML];             // row m=t*32+b -> embedding id
__device__ int   g_map3[ML];             // row m=b*512+t -> t*32+b
__device__ int   g_is64;
__device__ unsigned g_barcnt;            // persistent-scan barrier counter

// ---------------- f32x2 helpers ----------------
__device__ __forceinline__ u64 ffma2(u64 a, u64 b, u64 c){
    u64 d; asm("fma.rn.f32x2 %0, %1, %2, %3;" : "=l"(d) : "l"(a), "l"(b), "l"(c)); return d;
}
__device__ __forceinline__ u64 pack2(float x, float y){
    u64 r; unsigned xi = __float_as_uint(x), yi = __float_as_uint(y);
    asm("mov.b64 %0, {%1, %2};" : "=l"(r) : "r"(xi), "r"(yi)); return r;
}
__device__ __forceinline__ float2 unpack2(u64 v){
    unsigned lo, hi; asm("mov.b64 {%0, %1}, %2;" : "=r"(lo), "=r"(hi) : "l"(v));
    return make_float2(__uint_as_float(lo), __uint_as_float(hi));
}

// ---------------- grid barrier primitives (no L1 flush) ----------------
__device__ __forceinline__ void bar_arrive_release(unsigned* p){
    asm volatile("red.release.gpu.global.add.u32 [%0], 1;" :: "l"(p) : "memory");
}
__device__ __forceinline__ unsigned ld_acquire_gpu(const unsigned* p){
    unsigned v;
    asm volatile("ld.acquire.gpu.global.u32 %0, [%1];" : "=r"(v) : "l"(p) : "memory");
    return v;
}

// ---------------- id dtype detection (int32 vs int64) ----------------
__global__ void detect_kernel(const long long* __restrict__ x){
    if (threadIdx.x == 0 && blockIdx.x == 0){
        int ok = 1;
        #pragma unroll
        for (int i = 0; i < 16; i++){
            long long v = x[i];
            if (v < 0 || v >= VOCAB) ok = 0;
        }
        g_is64 = ok;
    }
}

__global__ void build_maps(const void* __restrict__ xraw){
    int i = blockIdx.x * blockDim.x + threadIdx.x;
    if (i == 0) g_barcnt = 0u;           // reset scan barrier every replay
    if (i >= ML) return;
    int is64 = g_is64;
    int t = i >> 5, b = i & 31;
    long long id = is64 ? ((const long long*)xraw)[b*SEQL + t]
                        : (long long)((const int*)xraw)[b*SEQL + t];
    g_map1[i] = (int)id;
    int b3 = i >> 9, t3 = i & 511;
    g_map3[i] = t3*32 + b3;
}

// ---------------- generic NT GEMM with gathered A rows ----------------
// C[m][n] = sum_k A[amap[m]][k] * B[n][k], K=1024.
// BM=BN=128, BK=16, 256 threads, 8x8 microtile, f32x2 FMAs, register prefetch.
__global__ __launch_bounds__(256,2) void gemm_nt(
    const float* __restrict__ A, const float* __restrict__ B,
    float* __restrict__ C, const int* __restrict__ amap, int ldc)
{
    __shared__ float As[16][132];
    __shared__ float Bs[16][132];
    __shared__ int sMap[128];
    const int tid = threadIdx.x;
    const int bn = blockIdx.x, bm = blockIdx.y;
    if (tid < 128) sMap[tid] = amap[bm*128 + tid];
    __syncthreads();

    const int tx = tid & 15, ty = tid >> 4;
    const int nBase = bn * 128;
    const int m0 = tid >> 2;
    const int k0 = (tid & 3) << 2;
    const int m1 = m0 + 64;

    u64 acc[8][4];
    #pragma unroll
    for (int r = 0; r < 8; r++)
        #pragma unroll
        for (int j = 0; j < 4; j++) acc[r][j] = 0ull;

    float4 pa0, pa1, pb0, pb1;
    pa0 = *(const float4*)(A + (size_t)sMap[m0]*HDIM + k0);
    pa1 = *(const float4*)(A + (size_t)sMap[m1]*HDIM + k0);
    pb0 = *(const float4*)(B + (size_t)(nBase + m0)*HDIM + k0);
    pb1 = *(const float4*)(B + (size_t)(nBase + m1)*HDIM + k0);

    for (int kt = 0; kt < 1024; kt += 16){
        As[k0  ][m0]=pa0.x; As[k0+1][m0]=pa0.y; As[k0+2][m0]=pa0.z; As[k0+3][m0]=pa0.w;
        As[k0  ][m1]=pa1.x; As[k0+1][m1]=pa1.y; As[k0+2][m1]=pa1.z; As[k0+3][m1]=pa1.w;
        Bs[k0  ][m0]=pb0.x; Bs[k0+1][m0]=pb0.y; Bs[k0+2][m0]=pb0.z; Bs[k0+3][m0]=pb0.w;
        Bs[k0  ][m1]=pb1.x; Bs[k0+1][m1]=pb1.y; Bs[k0+2][m1]=pb1.z; Bs[k0+3][m1]=pb1.w;
        __syncthreads();

        if (kt + 16 < 1024){
            int kn = kt + 16;
            pa0 = *(const float4*)(A + (size_t)sMap[m0]*HDIM + kn + k0);
            pa1 = *(const float4*)(A + (size_t)sMap[m1]*HDIM + kn + k0);
            pb0 = *(const float4*)(B + (size_t)(nBase + m0)*HDIM + kn + k0);
            pb1 = *(const float4*)(B + (size_t)(nBase + m1)*HDIM + kn + k0);
        }

        #pragma unroll
        for (int k = 0; k < 16; k++){
            ulonglong2 bq0 = *(const ulonglong2*)&Bs[k][tx*8];
            ulonglong2 bq1 = *(const ulonglong2*)&Bs[k][tx*8 + 4];
            float4 a0 = *(const float4*)&As[k][ty*8];
            float4 a1 = *(const float4*)&As[k][ty*8 + 4];
            float av[8] = {a0.x,a0.y,a0.z,a0.w,a1.x,a1.y,a1.z,a1.w};
            #pragma unroll
            for (int r = 0; r < 8; r++){
                u64 pa = pack2(av[r], av[r]);
                acc[r][0] = ffma2(pa, bq0.x, acc[r][0]);
                acc[r][1] = ffma2(pa, bq0.y, acc[r][1]);
                acc[r][2] = ffma2(pa, bq1.x, acc[r][2]);
                acc[r][3] = ffma2(pa, bq1.y, acc[r][3]);
            }
        }
        __syncthreads();
    }

    #pragma unroll
    for (int r = 0; r < 8; r++){
        float v[8];
        #pragma unroll
        for (int j = 0; j < 4; j++){
            float2 f = unpack2(acc[r][j]);
            v[2*j] = f.x; v[2*j+1] = f.y;
        }
        float* crow = C + (size_t)(bm*128 + ty*8 + r) * ldc + nBase + tx*8;
        *(float4*)(crow)     = make_float4(v[0], v[1], v[2], v[3]);
        *(float4*)(crow + 4) = make_float4(v[4], v[5], v[6], v[7]);
    }
}

// ---------------- persistent recurrent scan ----------------
// ONE kernel for all 512 steps. 128 CTAs co-resident, cg-style release/acquire
// grid barrier between steps (NO __threadfence -> no per-step L1D flush).
// W_h slice lives in REGISTERS (step-invariant). pre[t] is prefetched at step
// top so its DRAM latency hides under the h load + compute.
__global__ __launch_bounds__(256,1) void scan_kernel(
    const float* __restrict__ hidden0, const float* __restrict__ W_h,
    const float* __restrict__ pre, float* __restrict__ hout)
{
    __shared__ float sh[8*HDIM];           // 32 KB: h_prev for 8 batches
    __shared__ float red[8*8*32];          // 8 KB: partials [ks][b][cp]
    const int tid = threadIdx.x;
    const int bg = blockIdx.x >> 5, cg = blockIdx.x & 31;
    const int cp = tid & 31, ks = tid >> 5;
    const int col = cg*32 + cp;

    // step-invariant W_h[col][ks*128 .. +128) in registers (32 x 16B)
    ulonglong2 wreg[32];
    {
        const ulonglong2* wp = (const ulonglong2*)(W_h + (size_t)col*HDIM + ks*128);
        #pragma unroll
        for (int i = 0; i < 32; i++) wreg[i] = wp[i];
    }

    // this thread's output element (reduce role): batch b2=ks, col c2=cp
    const int gb = bg*8 + ks;
    const size_t ocol = (size_t)gb*HDIM + cg*32 + cp;

    for (int t = 0; t < SEQL; t++){
        // prefetch pre[t] for this thread's output element (independent of h)
        const float preval = pre[(size_t)t*BATCH*HDIM + ocol];

        // load h_prev slice (contiguous 32 KB) into SMEM
        const float4* src = (const float4*)((t == 0)
            ? (hidden0 + (size_t)bg*8*HDIM)
            : (hout + ((size_t)(t-1)*BATCH + bg*8)*HDIM));
        float4* dst = (float4*)sh;
        #pragma unroll
        for (int i = 0; i < 8; i++) dst[tid + i*256] = src[tid + i*256];
        __syncthreads();

        u64 acc[8];
        #pragma unroll
        for (int b = 0; b < 8; b++) acc[b] = 0ull;

        const ulonglong2* hb = (const ulonglong2*)sh;  // [b*256 + ks*32 + q]
        #pragma unroll
        for (int q = 0; q < 32; q++){
            ulonglong2 w = wreg[q];
            #pragma unroll
            for (int b = 0; b < 8; b++){
                ulonglong2 h = hb[b*256 + ks*32 + q];   // broadcast LDS.128
                acc[b] = ffma2(w.x, h.x, acc[b]);
                acc[b] = ffma2(w.y, h.y, acc[b]);
            }
        }

        #pragma unroll
        for (int b = 0; b < 8; b++){
            float2 f = unpack2(acc[b]);
            red[(ks*8 + b)*32 + cp] = f.x + f.y;
        }
        __syncthreads();

        // reduce 8 K-chunks; thread tid -> (batch ks, col cp)
        {
            float dot = 0.f;
            #pragma unroll
            for (int k2 = 0; k2 < 8; k2++) dot += red[(k2*8 + ks)*32 + cp];
            hout[(size_t)t*BATCH*HDIM + ocol] = tanhf(dot + preval);
        }

        // cg-style grid barrier: syncthreads -> release-add -> acquire-poll
        if (t + 1 < SEQL){
            __syncthreads();
            if (tid == 0){
                bar_arrive_release(&g_barcnt);
                const unsigned target = 128u*(unsigned)(t+1);
                while (ld_acquire_gpu(&g_barcnt) < target) { }
            }
            __syncthreads();
        }
    }
}

__global__ void copy_hidden(float* __restrict__ dst){
    int i = blockIdx.x * blockDim.x + threadIdx.x;
    dst[i] = g_hout[(size_t)(511*32)*HDIM + i];
}

extern "C" void kernel_launch(void* const* d_in, const int* in_sizes, int n_in,
                              void* d_out, int out_size) {
    const void*  x      = d_in[0];
    const float* hidden = (const float*)d_in[1];
    const float* emb    = (const float*)d_in[2];
    const float* W_h    = (const float*)d_in[3];
    const float* W_e    = (const float*)d_in[4];
    const float* W_o    = (const float*)d_in[5];
    float* out = (float*)d_out;

    float *pre, *hout; int *map1, *map3;
    cudaGetSymbolAddress((void**)&pre,  g_pre);
    cudaGetSymbolAddress((void**)&hout, g_hout);
    cudaGetSymbolAddress((void**)&map1, g_map1);
    cudaGetSymbolAddress((void**)&map3, g_map3);

    detect_kernel<<<1, 32>>>((const long long*)x);
    build_maps<<<64, 256>>>(x);

    // Phase 1: pre = emb[x] @ W_e^T   (M=16384, N=1024)
    gemm_nt<<<dim3(8, 128), 256>>>(emb, W_e, pre, map1, HDIM);

    // Phase 2: persistent scan, all 512 steps in ONE kernel
    scan_kernel<<<128, 256>>>(hidden, W_h, pre, hout);

    // Phase 3: logits = outputs @ W_o^T   (M=16384 rows b*512+t, N=8192)
    gemm_nt<<<dim3(64, 128), 256>>>(hout, W_o, out, map3, VOCAB);

    if (out_size >= LOGITS_ELEMS + BATCH*HDIM)
        copy_hidden<<<32, 1024>>>(out + LOGITS_ELEMS);
}

// round 5
// speedup vs baseline: 1.0062x; 1.0062x over previous
#include <cuda_runtime.h>
#include <cuda_bf16.h>

typedef unsigned long long u64;

#define SEQL   512
#define BATCH  32
#define HDIM   1024
#define VOCAB  8192
#define ML     (BATCH*SEQL)              /* 16384 */
#define LOGITS_ELEMS 134217728           /* 32*512*8192 */

// ---------------- scratch (cudaMalloc forbidden) ----------------
__device__ float g_pre[ML*HDIM];         // 64 MB, layout [t][b][h]
__device__ float g_hout[ML*HDIM];        // 64 MB, layout [t][b][h]
__device__ int   g_map1[ML];             // row m=t*32+b -> embedding id
__device__ int   g_map3[ML];             // row m=b*512+t -> t*32+b
__device__ int   g_is64;
__device__ unsigned g_bar4[4*64];        // per-batch-group barrier counters, 256B apart

// ---------------- f32x2 helpers ----------------
__device__ __forceinline__ u64 ffma2(u64 a, u64 b, u64 c){
    u64 d; asm("fma.rn.f32x2 %0, %1, %2, %3;" : "=l"(d) : "l"(a), "l"(b), "l"(c)); return d;
}
__device__ __forceinline__ u64 pack2(float x, float y){
    u64 r; unsigned xi = __float_as_uint(x), yi = __float_as_uint(y);
    asm("mov.b64 %0, {%1, %2};" : "=l"(r) : "r"(xi), "r"(yi)); return r;
}
__device__ __forceinline__ float2 unpack2(u64 v){
    unsigned lo, hi; asm("mov.b64 {%0, %1}, %2;" : "=r"(lo), "=r"(hi) : "l"(v));
    return make_float2(__uint_as_float(lo), __uint_as_float(hi));
}

// ---------------- grid barrier primitives ----------------
__device__ __forceinline__ void bar_arrive_release(unsigned* p){
    asm volatile("red.release.gpu.global.add.u32 [%0], 1;" :: "l"(p) : "memory");
}
__device__ __forceinline__ unsigned ld_acquire_gpu(const unsigned* p){
    unsigned v;
    asm volatile("ld.acquire.gpu.global.u32 %0, [%1];" : "=r"(v) : "l"(p) : "memory");
    return v;
}

// ---------------- id dtype detection (int32 vs int64) ----------------
__global__ void detect_kernel(const long long* __restrict__ x){
    if (threadIdx.x == 0 && blockIdx.x == 0){
        int ok = 1;
        #pragma unroll
        for (int i = 0; i < 16; i++){
            long long v = x[i];
            if (v < 0 || v >= VOCAB) ok = 0;
        }
        g_is64 = ok;
    }
}

__global__ void build_maps(const void* __restrict__ xraw){
    int i = blockIdx.x * blockDim.x + threadIdx.x;
    if (i < 4*64) g_bar4[i] = 0u;        // reset scan barriers every replay
    if (i >= ML) return;
    int is64 = g_is64;
    int t = i >> 5, b = i & 31;
    long long id = is64 ? ((const long long*)xraw)[b*SEQL + t]
                        : (long long)((const int*)xraw)[b*SEQL + t];
    g_map1[i] = (int)id;
    int b3 = i >> 9, t3 = i & 511;
    g_map3[i] = t3*32 + b3;
}

// ---------------- generic NT GEMM with gathered A rows ----------------
// C[m][n] = sum_k A[amap[m]][k] * B[n][k], K=1024.
// BM=BN=128, BK=16, 256 threads, 8x8 microtile, f32x2 FMAs, register prefetch.
__global__ __launch_bounds__(256,2) void gemm_nt(
    const float* __restrict__ A, const float* __restrict__ B,
    float* __restrict__ C, const int* __restrict__ amap, int ldc)
{
    __shared__ float As[16][132];
    __shared__ float Bs[16][132];
    __shared__ int sMap[128];
    const int tid = threadIdx.x;
    const int bn = blockIdx.x, bm = blockIdx.y;
    if (tid < 128) sMap[tid] = amap[bm*128 + tid];
    __syncthreads();

    const int tx = tid & 15, ty = tid >> 4;
    const int nBase = bn * 128;
    const int m0 = tid >> 2;
    const int k0 = (tid & 3) << 2;
    const int m1 = m0 + 64;

    u64 acc[8][4];
    #pragma unroll
    for (int r = 0; r < 8; r++)
        #pragma unroll
        for (int j = 0; j < 4; j++) acc[r][j] = 0ull;

    float4 pa0, pa1, pb0, pb1;
    pa0 = *(const float4*)(A + (size_t)sMap[m0]*HDIM + k0);
    pa1 = *(const float4*)(A + (size_t)sMap[m1]*HDIM + k0);
    pb0 = *(const float4*)(B + (size_t)(nBase + m0)*HDIM + k0);
    pb1 = *(const float4*)(B + (size_t)(nBase + m1)*HDIM + k0);

    for (int kt = 0; kt < 1024; kt += 16){
        As[k0  ][m0]=pa0.x; As[k0+1][m0]=pa0.y; As[k0+2][m0]=pa0.z; As[k0+3][m0]=pa0.w;
        As[k0  ][m1]=pa1.x; As[k0+1][m1]=pa1.y; As[k0+2][m1]=pa1.z; As[k0+3][m1]=pa1.w;
        Bs[k0  ][m0]=pb0.x; Bs[k0+1][m0]=pb0.y; Bs[k0+2][m0]=pb0.z; Bs[k0+3][m0]=pb0.w;
        Bs[k0  ][m1]=pb1.x; Bs[k0+1][m1]=pb1.y; Bs[k0+2][m1]=pb1.z; Bs[k0+3][m1]=pb1.w;
        __syncthreads();

        if (kt + 16 < 1024){
            int kn = kt + 16;
            pa0 = *(const float4*)(A + (size_t)sMap[m0]*HDIM + kn + k0);
            pa1 = *(const float4*)(A + (size_t)sMap[m1]*HDIM + kn + k0);
            pb0 = *(const float4*)(B + (size_t)(nBase + m0)*HDIM + kn + k0);
            pb1 = *(const float4*)(B + (size_t)(nBase + m1)*HDIM + kn + k0);
        }

        #pragma unroll
        for (int k = 0; k < 16; k++){
            ulonglong2 bq0 = *(const ulonglong2*)&Bs[k][tx*8];
            ulonglong2 bq1 = *(const ulonglong2*)&Bs[k][tx*8 + 4];
            float4 a0 = *(const float4*)&As[k][ty*8];
            float4 a1 = *(const float4*)&As[k][ty*8 + 4];
            float av[8] = {a0.x,a0.y,a0.z,a0.w,a1.x,a1.y,a1.z,a1.w};
            #pragma unroll
            for (int r = 0; r < 8; r++){
                u64 pa = pack2(av[r], av[r]);
                acc[r][0] = ffma2(pa, bq0.x, acc[r][0]);
                acc[r][1] = ffma2(pa, bq0.y, acc[r][1]);
                acc[r][2] = ffma2(pa, bq1.x, acc[r][2]);
                acc[r][3] = ffma2(pa, bq1.y, acc[r][3]);
            }
        }
        __syncthreads();
    }

    #pragma unroll
    for (int r = 0; r < 8; r++){
        float v[8];
        #pragma unroll
        for (int j = 0; j < 4; j++){
            float2 f = unpack2(acc[r][j]);
            v[2*j] = f.x; v[2*j+1] = f.y;
        }
        float* crow = C + (size_t)(bm*128 + ty*8 + r) * ldc + nBase + tx*8;
        *(float4*)(crow)     = make_float4(v[0], v[1], v[2], v[3]);
        *(float4*)(crow + 4) = make_float4(v[4], v[5], v[6], v[7]);
    }
}

// ---------------- persistent recurrent scan ----------------
// ONE kernel for all 512 steps. 128 CTAs = 4 INDEPENDENT batch-group chains
// x 32 col-group CTAs. Each chain has its OWN 32-arrival barrier (counters on
// separate 256B-spaced addresses -> different LTS slices): 4x less atomic
// serialization, no cross-chain straggler coupling. W_h slice in REGISTERS.
__global__ __launch_bounds__(256,1) void scan_kernel(
    const float* __restrict__ hidden0, const float* __restrict__ W_h,
    const float* __restrict__ pre, float* __restrict__ hout)
{
    __shared__ float sh[8*HDIM];           // 32 KB: h_prev for 8 batches
    __shared__ float red[8*8*32];          // 8 KB: partials [ks][b][cp]
    const int tid = threadIdx.x;
    const int bg = blockIdx.x >> 5, cg = blockIdx.x & 31;
    const int cp = tid & 31, ks = tid >> 5;
    const int col = cg*32 + cp;
    unsigned* bar = &g_bar4[bg*64];

    // step-invariant W_h[col][ks*128 .. +128) in registers (32 x 16B)
    ulonglong2 wreg[32];
    {
        const ulonglong2* wp = (const ulonglong2*)(W_h + (size_t)col*HDIM + ks*128);
        #pragma unroll
        for (int i = 0; i < 32; i++) wreg[i] = wp[i];
    }

    // this thread's output element (reduce role): batch b2=ks, col c2=cp
    const int gb = bg*8 + ks;
    const size_t ocol = (size_t)gb*HDIM + cg*32 + cp;

    for (int t = 0; t < SEQL; t++){
        // prefetch pre[t] for this thread's output element (independent of h)
        const float preval = pre[(size_t)t*BATCH*HDIM + ocol];

        // load h_prev slice (contiguous 32 KB) into SMEM
        const float4* src = (const float4*)((t == 0)
            ? (hidden0 + (size_t)bg*8*HDIM)
            : (hout + ((size_t)(t-1)*BATCH + bg*8)*HDIM));
        float4* dst = (float4*)sh;
        #pragma unroll
        for (int i = 0; i < 8; i++) dst[tid + i*256] = src[tid + i*256];
        __syncthreads();

        u64 acc[8];
        #pragma unroll
        for (int b = 0; b < 8; b++) acc[b] = 0ull;

        const ulonglong2* hb = (const ulonglong2*)sh;  // [b*256 + ks*32 + q]
        #pragma unroll
        for (int q = 0; q < 32; q++){
            ulonglong2 w = wreg[q];
            #pragma unroll
            for (int b = 0; b < 8; b++){
                ulonglong2 h = hb[b*256 + ks*32 + q];   // broadcast LDS.128
                acc[b] = ffma2(w.x, h.x, acc[b]);
                acc[b] = ffma2(w.y, h.y, acc[b]);
            }
        }

        #pragma unroll
        for (int b = 0; b < 8; b++){
            float2 f = unpack2(acc[b]);
            red[(ks*8 + b)*32 + cp] = f.x + f.y;
        }
        __syncthreads();

        // reduce 8 K-chunks; thread tid -> (batch ks, col cp)
        {
            float dot = 0.f;
            #pragma unroll
            for (int k2 = 0; k2 < 8; k2++) dot += red[(k2*8 + ks)*32 + cp];
            hout[(size_t)t*BATCH*HDIM + ocol] = tanhf(dot + preval);
        }

        // per-chain grid barrier (32 arrivals), backoff poll
        if (t + 1 < SEQL){
            __syncthreads();
            if (tid == 0){
                bar_arrive_release(bar);
                const unsigned target = 32u*(unsigned)(t+1);
                if (ld_acquire_gpu(bar) < target){
                    while (ld_acquire_gpu(bar) < target) __nanosleep(64);
                }
            }
            __syncthreads();
        }
    }
}

__global__ void copy_hidden(float* __restrict__ dst){
    int i = blockIdx.x * blockDim.x + threadIdx.x;
    dst[i] = g_hout[(size_t)(511*32)*HDIM + i];
}

extern "C" void kernel_launch(void* const* d_in, const int* in_sizes, int n_in,
                              void* d_out, int out_size) {
    const void*  x      = d_in[0];
    const float* hidden = (const float*)d_in[1];
    const float* emb    = (const float*)d_in[2];
    const float* W_h    = (const float*)d_in[3];
    const float* W_e    = (const float*)d_in[4];
    const float* W_o    = (const float*)d_in[5];
    float* out = (float*)d_out;

    float *pre, *hout; int *map1, *map3;
    cudaGetSymbolAddress((void**)&pre,  g_pre);
    cudaGetSymbolAddress((void**)&hout, g_hout);
    cudaGetSymbolAddress((void**)&map1, g_map1);
    cudaGetSymbolAddress((void**)&map3, g_map3);

    detect_kernel<<<1, 32>>>((const long long*)x);
    build_maps<<<64, 256>>>(x);

    // Phase 1: pre = emb[x] @ W_e^T   (M=16384, N=1024)
    gemm_nt<<<dim3(8, 128), 256>>>(emb, W_e, pre, map1, HDIM);

    // Phase 2: persistent scan, all 512 steps in ONE kernel
    scan_kernel<<<128, 256>>>(hidden, W_h, pre, hout);

    // Phase 3: logits = outputs @ W_o^T   (M=16384 rows b*512+t, N=8192)
    gemm_nt<<<dim3(64, 128), 256>>>(hout, W_o, out, map3, VOCAB);

    if (out_size >= LOGITS_ELEMS + BATCH*HDIM)
        copy_hidden<<<32, 1024>>>(out + LOGITS_ELEMS);
}

// round 7
// speedup vs baseline: 1.6729x; 1.6626x over previous
#include <cuda_runtime.h>
#include <cuda_bf16.h>
#include <cstdint>

typedef unsigned long long u64;

#define SEQL   512
#define BATCH  32
#define HDIM   1024
#define VOCAB  8192
#define ML     (BATCH*SEQL)              /* 16384 */
#define LOGITS_ELEMS 134217728           /* 32*512*8192 */
#define K3     3072                      /* split-K: [hi|hi|lo] x [hi|lo|hi] */
#define NCH    96                        /* K3 / 32 */
#define STRIDE 40                        /* smem row stride in bf16 (80 B) */

// ---------------- scratch (cudaMalloc forbidden) ----------------
__device__ float g_pre[ML*HDIM];                 // 64 MB, [t][b][h]
__device__ float g_hout[ML*HDIM];                // 64 MB, [t][b][h]
__device__ __nv_bfloat16 g_abig[(size_t)ML*K3];  // 96 MB: split A (phase1 then phase3)
__device__ __nv_bfloat16 g_bo[(size_t)VOCAB*K3]; // 48 MB: split W_o
__device__ __nv_bfloat16 g_be[(size_t)HDIM*K3];  //  6 MB: split W_e
__device__ int   g_map1[ML];             // row m=t*32+b -> embedding id
__device__ int   g_map3[ML];             // row m=b*512+t -> t*32+b
__device__ int   g_is64;
__device__ unsigned g_bar4[4*64];        // per-batch-group barrier counters

// ---------------- f32x2 helpers ----------------
__device__ __forceinline__ u64 ffma2(u64 a, u64 b, u64 c){
    u64 d; asm("fma.rn.f32x2 %0, %1, %2, %3;" : "=l"(d) : "l"(a), "l"(b), "l"(c)); return d;
}
__device__ __forceinline__ float2 unpack2(u64 v){
    unsigned lo, hi; asm("mov.b64 {%0, %1}, %2;" : "=r"(lo), "=r"(hi) : "l"(v));
    return make_float2(__uint_as_float(lo), __uint_as_float(hi));
}

// ---------------- barrier primitives ----------------
__device__ __forceinline__ void bar_arrive_release(unsigned* p){
    asm volatile("red.release.gpu.global.add.u32 [%0], 1;" :: "l"(p) : "memory");
}
__device__ __forceinline__ unsigned ld_acquire_gpu(const unsigned* p){
    unsigned v;
    asm volatile("ld.acquire.gpu.global.u32 %0, [%1];" : "=r"(v) : "l"(p) : "memory");
    return v;
}

// ---------------- sm80-class tensor primitives (valid on plain sm_103) ----------------
__device__ __forceinline__ unsigned smem_u32(const void* p){
    unsigned a;
    asm("{ .reg .u64 t; cvta.to.shared.u64 t, %1; cvt.u32.u64 %0, t; }" : "=r"(a) : "l"(p));
    return a;
}
__device__ __forceinline__ void ldsm4(unsigned* r, unsigned addr){
    asm volatile("ldmatrix.sync.aligned.m8n8.x4.shared.b16 {%0,%1,%2,%3}, [%4];"
        : "=r"(r[0]), "=r"(r[1]), "=r"(r[2]), "=r"(r[3]) : "r"(addr));
}
__device__ __forceinline__ void mma16816(float* d, const unsigned* a, const unsigned* b){
    asm volatile(
        "mma.sync.aligned.m16n8k16.row.col.f32.bf16.bf16.f32 "
        "{%0,%1,%2,%3}, {%4,%5,%6,%7}, {%8,%9}, {%0,%1,%2,%3};"
        : "+f"(d[0]), "+f"(d[1]), "+f"(d[2]), "+f"(d[3])
        : "r"(a[0]), "r"(a[1]), "r"(a[2]), "r"(a[3]), "r"(b[0]), "r"(b[1]));
}
__device__ __forceinline__ void cpasync16(unsigned saddr, const void* g){
    asm volatile("cp.async.cg.shared.global [%0], [%1], 16;" :: "r"(saddr), "l"(g) : "memory");
}
__device__ __forceinline__ void cp_commit(){
    asm volatile("cp.async.commit_group;" ::: "memory");
}
__device__ __forceinline__ void cp_wait0(){
    asm volatile("cp.async.wait_group 0;" ::: "memory");
}

// ---------------- id dtype detection / maps ----------------
__global__ void detect_kernel(const long long* __restrict__ x){
    if (threadIdx.x == 0 && blockIdx.x == 0){
        int ok = 1;
        #pragma unroll
        for (int i = 0; i < 16; i++){
            long long v = x[i];
            if (v < 0 || v >= VOCAB) ok = 0;
        }
        g_is64 = ok;
    }
}

__global__ void build_maps(const void* __restrict__ xraw){
    int i = blockIdx.x * blockDim.x + threadIdx.x;
    if (i < 4*64) g_bar4[i] = 0u;
    if (i >= ML) return;
    int is64 = g_is64;
    int t = i >> 5, b = i & 31;
    long long id = is64 ? ((const long long*)xraw)[b*SEQL + t]
                        : (long long)((const int*)xraw)[b*SEQL + t];
    g_map1[i] = (int)id;
    int b3 = i >> 9, t3 = i & 511;
    g_map3[i] = t3*32 + b3;
}

// ---------------- fp32 -> bf16 hi/lo split conversions ----------------
// A row (K3): [hi | hi | lo], gathered rows. B row (K3): [hi | lo | hi].
__global__ void convA_kernel(const float* __restrict__ src, __nv_bfloat16* __restrict__ dst,
                             const int* __restrict__ map){
    int i = blockIdx.x * blockDim.x + threadIdx.x;   // over ML*1024
    int r = i >> 10, k = i & 1023;
    float v = src[(size_t)map[r]*HDIM + k];
    __nv_bfloat16 h = __float2bfloat16(v);
    __nv_bfloat16 l = __float2bfloat16(v - __bfloat162float(h));
    size_t base = (size_t)r * K3;
    dst[base + k] = h; dst[base + 1024 + k] = h; dst[base + 2048 + k] = l;
}
__global__ void convB_kernel(const float* __restrict__ src, __nv_bfloat16* __restrict__ dst){
    int i = blockIdx.x * blockDim.x + threadIdx.x;   // over rows*1024
    int r = i >> 10, k = i & 1023;
    float v = src[(size_t)r*HDIM + k];
    __nv_bfloat16 h = __float2bfloat16(v);
    __nv_bfloat16 l = __float2bfloat16(v - __bfloat162float(h));
    size_t base = (size_t)r * K3;
    dst[base + k] = h; dst[base + 1024 + k] = l; dst[base + 2048 + k] = h;
}

// ---------------- bf16 NT GEMM via mma.sync (HMMA) ----------------
// C[m][n] = sum_k A[bm*128+m][k] * B[bn*128+n][k], K=K3, fp32 accum.
// 128x128x32 tile, 256 threads = 8 warps (4m x 2n), warp tile 32x64,
// cp.async double buffer, padded-80B SMEM rows (conflict-free ldmatrix).
__global__ __launch_bounds__(256) void gemm_tc(
    const __nv_bfloat16* __restrict__ A, const __nv_bfloat16* __restrict__ B,
    float* __restrict__ C, int ldc)
{
    __shared__ __align__(16) __nv_bfloat16 smem[2][2][128*STRIDE];  // [stage][A/B]
    const int tid = threadIdx.x, wid = tid >> 5, lane = tid & 31;
    const int bn = blockIdx.x, bm = blockIdx.y;

    const unsigned sbase = smem_u32(&smem[0][0][0]);
    const unsigned stageB = 128*STRIDE*2;          // bytes per matrix (10240)
    // stage s: A at sbase + s*2*stageB, B at +stageB

    const __nv_bfloat16* Abase = A + (size_t)(bm*128)*K3;
    const __nv_bfloat16* Bbase = B + (size_t)(bn*128)*K3;

    // gmem->smem: 512 uint4 per matrix, 2 per thread per matrix
    const int r0 = tid >> 2,        sg0 = (tid & 3);
    const int r1 = (tid + 256) >> 2, sg1 = sg0;

    auto issue_stage = [&](int c, int s){
        unsigned offA = sbase + (unsigned)s*2*stageB;
        unsigned offB = offA + stageB;
        const __nv_bfloat16* ga0 = Abase + (size_t)r0*K3 + c*32 + sg0*8;
        const __nv_bfloat16* ga1 = Abase + (size_t)r1*K3 + c*32 + sg1*8;
        const __nv_bfloat16* gb0 = Bbase + (size_t)r0*K3 + c*32 + sg0*8;
        const __nv_bfloat16* gb1 = Bbase + (size_t)r1*K3 + c*32 + sg1*8;
        cpasync16(offA + r0*80 + sg0*16, ga0);
        cpasync16(offA + r1*80 + sg1*16, ga1);
        cpasync16(offB + r0*80 + sg0*16, gb0);
        cpasync16(offB + r1*80 + sg1*16, gb1);
        cp_commit();
    };

    // warp tile: wm in {0,32,64,96}, wn in {0,64}
    const int wm = (wid >> 1)*32;
    const int wn = (wid & 1)*64;
    const int g = lane >> 3, r8 = lane & 7;

    float acc[2][8][4];
    #pragma unroll
    for (int mm = 0; mm < 2; mm++)
        #pragma unroll
        for (int nn = 0; nn < 8; nn++)
            #pragma unroll
            for (int j = 0; j < 4; j++) acc[mm][nn][j] = 0.f;

    issue_stage(0, 0);

    for (int c = 0; c < NCH; c++){
        const int s = c & 1;
        cp_wait0();
        __syncthreads();
        if (c + 1 < NCH) issue_stage(c + 1, s ^ 1);

        const unsigned offA = sbase + (unsigned)s*2*stageB;
        const unsigned offB = offA + stageB;
        #pragma unroll
        for (int ks = 0; ks < 2; ks++){
            unsigned af[2][4], bf[4][4];
            #pragma unroll
            for (int mm = 0; mm < 2; mm++){
                unsigned addr = offA + (unsigned)(wm + mm*16 + r8 + (g & 1)*8)*80
                              + ks*32 + (g >> 1)*16;
                ldsm4(af[mm], addr);
            }
            #pragma unroll
            for (int nt = 0; nt < 4; nt++){
                unsigned addr = offB + (unsigned)(wn + nt*16 + r8 + (g >> 1)*8)*80
                              + ks*32 + (g & 1)*16;
                ldsm4(bf[nt], addr);
            }
            #pragma unroll
            for (int mm = 0; mm < 2; mm++)
                #pragma unroll
                for (int nt = 0; nt < 4; nt++){
                    mma16816(acc[mm][2*nt],   af[mm], &bf[nt][0]);
                    mma16816(acc[mm][2*nt+1], af[mm], &bf[nt][2]);
                }
        }
        __syncthreads();
    }

    // epilogue: thread holds D[row = wm+mm*16 + lane/4 (+8)][col = wn+nn*8 + 2*(lane%4)]
    const int erow = lane >> 2, ecol = (lane & 3)*2;
    #pragma unroll
    for (int mm = 0; mm < 2; mm++){
        #pragma unroll
        for (int nn = 0; nn < 8; nn++){
            size_t row = (size_t)(bm*128 + wm + mm*16 + erow);
            size_t col = (size_t)(bn*128 + wn + nn*8 + ecol);
            *(float2*)&C[row*ldc + col]       = make_float2(acc[mm][nn][0], acc[mm][nn][1]);
            *(float2*)&C[(row + 8)*ldc + col] = make_float2(acc[mm][nn][2], acc[mm][nn][3]);
        }
    }
}

// ---------------- persistent recurrent scan (unchanged) ----------------
__global__ __launch_bounds__(256,1) void scan_kernel(
    const float* __restrict__ hidden0, const float* __restrict__ W_h,
    const float* __restrict__ pre, float* __restrict__ hout)
{
    __shared__ float sh[8*HDIM];
    __shared__ float red[8*8*32];
    const int tid = threadIdx.x;
    const int bg = blockIdx.x >> 5, cg = blockIdx.x & 31;
    const int cp = tid & 31, ks = tid >> 5;
    const int col = cg*32 + cp;
    unsigned* bar = &g_bar4[bg*64];

    ulonglong2 wreg[32];
    {
        const ulonglong2* wp = (const ulonglong2*)(W_h + (size_t)col*HDIM + ks*128);
        #pragma unroll
        for (int i = 0; i < 32; i++) wreg[i] = wp[i];
    }

    const int gb = bg*8 + ks;
    const size_t ocol = (size_t)gb*HDIM + cg*32 + cp;

    for (int t = 0; t < SEQL; t++){
        const float preval = pre[(size_t)t*BATCH*HDIM + ocol];

        const float4* src = (const float4*)((t == 0)
            ? (hidden0 + (size_t)bg*8*HDIM)
            : (hout + ((size_t)(t-1)*BATCH + bg*8)*HDIM));
        float4* dst = (float4*)sh;
        #pragma unroll
        for (int i = 0; i < 8; i++) dst[tid + i*256] = src[tid + i*256];
        __syncthreads();

        u64 acc[8];
        #pragma unroll
        for (int b = 0; b < 8; b++) acc[b] = 0ull;

        const ulonglong2* hb = (const ulonglong2*)sh;
        #pragma unroll
        for (int q = 0; q < 32; q++){
            ulonglong2 w = wreg[q];
            #pragma unroll
            for (int b = 0; b < 8; b++){
                ulonglong2 h = hb[b*256 + ks*32 + q];
                acc[b] = ffma2(w.x, h.x, acc[b]);
                acc[b] = ffma2(w.y, h.y, acc[b]);
            }
        }

        #pragma unroll
        for (int b = 0; b < 8; b++){
            float2 f = unpack2(acc[b]);
            red[(ks*8 + b)*32 + cp] = f.x + f.y;
        }
        __syncthreads();

        {
            float dot = 0.f;
            #pragma unroll
            for (int k2 = 0; k2 < 8; k2++) dot += red[(k2*8 + ks)*32 + cp];
            hout[(size_t)t*BATCH*HDIM + ocol] = tanhf(dot + preval);
        }

        if (t + 1 < SEQL){
            __syncthreads();
            if (tid == 0){
                bar_arrive_release(bar);
                const unsigned target = 32u*(unsigned)(t+1);
                if (ld_acquire_gpu(bar) < target){
                    while (ld_acquire_gpu(bar) < target) __nanosleep(64);
                }
            }
            __syncthreads();
        }
    }
}

__global__ void copy_hidden(float* __restrict__ dst){
    int i = blockIdx.x * blockDim.x + threadIdx.x;
    dst[i] = g_hout[(size_t)(511*32)*HDIM + i];
}

extern "C" void kernel_launch(void* const* d_in, const int* in_sizes, int n_in,
                              void* d_out, int out_size) {
    const void*  x      = d_in[0];
    const float* hidden = (const float*)d_in[1];
    const float* emb    = (const float*)d_in[2];
    const float* W_h    = (const float*)d_in[3];
    const float* W_e    = (const float*)d_in[4];
    const float* W_o    = (const float*)d_in[5];
    float* out = (float*)d_out;

    float *pre, *hout; int *map1, *map3; __nv_bfloat16 *abig, *bo, *be;
    cudaGetSymbolAddress((void**)&pre,  g_pre);
    cudaGetSymbolAddress((void**)&hout, g_hout);
    cudaGetSymbolAddress((void**)&map1, g_map1);
    cudaGetSymbolAddress((void**)&map3, g_map3);
    cudaGetSymbolAddress((void**)&abig, g_abig);
    cudaGetSymbolAddress((void**)&bo,   g_bo);
    cudaGetSymbolAddress((void**)&be,   g_be);

    detect_kernel<<<1, 32>>>((const long long*)x);
    build_maps<<<64, 256>>>(x);

    // Phase 1: pre = emb[x] @ W_e^T via HMMA (A = gathered split emb)
    convB_kernel<<<HDIM*HDIM/256, 256>>>(W_e, be);
    convA_kernel<<<ML*HDIM/256, 256>>>(emb, abig, map1);
    gemm_tc<<<dim3(8, 128), 256>>>(abig, be, pre, HDIM);

    // Phase 2: persistent scan
    scan_kernel<<<128, 256>>>(hidden, W_h, pre, hout);

    // Phase 3: logits = outputs @ W_o^T via HMMA (A = gathered split hout)
    convB_kernel<<<VOCAB*HDIM/256, 256>>>(W_o, bo);
    convA_kernel<<<ML*HDIM/256, 256>>>(hout, abig, map3);
    gemm_tc<<<dim3(64, 128), 256>>>(abig, bo, out, VOCAB);

    if (out_size >= LOGITS_ELEMS + BATCH*HDIM)
        copy_hidden<<<32, 1024>>>(out + LOGITS_ELEMS);
}

// round 8
// speedup vs baseline: 1.8616x; 1.1128x over previous
#include <cuda_runtime.h>
#include <cuda_bf16.h>
#include <cstdint>

typedef unsigned long long u64;

#define SEQL   512
#define BATCH  32
#define HDIM   1024
#define VOCAB  8192
#define ML     (BATCH*SEQL)              /* 16384 */
#define LOGITS_ELEMS 134217728           /* 32*512*8192 */
#define K3     3072                      /* split-K: [hi|hi|lo] x [hi|lo|hi] */
#define BK     64
#define KCH    48                        /* K3 / BK */
#define STAGE_BYTES 49152                /* (256+128)*64*2 */

// ---------------- scratch (cudaMalloc forbidden) ----------------
__device__ float g_pre[ML*HDIM];                 // 64 MB, [t][b][h]
__device__ float g_hout[ML*HDIM];                // 64 MB, [t][b][h]
__device__ __nv_bfloat16 g_abig[(size_t)ML*K3];  // 96 MB: split A (phase1 then phase3)
__device__ __nv_bfloat16 g_bo[(size_t)VOCAB*K3]; // 48 MB: split W_o
__device__ __nv_bfloat16 g_be[(size_t)HDIM*K3];  //  6 MB: split W_e
__device__ int   g_map1[ML];             // row m=t*32+b -> embedding id
__device__ int   g_map3[ML];             // row m=b*512+t -> t*32+b
__device__ int   g_is64;
__device__ unsigned g_bar4[4*64];        // per-batch-group barrier counters

// ---------------- f32x2 helpers ----------------
__device__ __forceinline__ u64 ffma2(u64 a, u64 b, u64 c){
    u64 d; asm("fma.rn.f32x2 %0, %1, %2, %3;" : "=l"(d) : "l"(a), "l"(b), "l"(c)); return d;
}
__device__ __forceinline__ float2 unpack2(u64 v){
    unsigned lo, hi; asm("mov.b64 {%0, %1}, %2;" : "=r"(lo), "=r"(hi) : "l"(v));
    return make_float2(__uint_as_float(lo), __uint_as_float(hi));
}

// ---------------- barrier primitives ----------------
__device__ __forceinline__ void bar_arrive_release(unsigned* p){
    asm volatile("red.release.gpu.global.add.u32 [%0], 1;" :: "l"(p) : "memory");
}
__device__ __forceinline__ unsigned ld_acquire_gpu(const unsigned* p){
    unsigned v;
    asm volatile("ld.acquire.gpu.global.u32 %0, [%1];" : "=r"(v) : "l"(p) : "memory");
    return v;
}

// ---------------- sm80-class tensor primitives (valid on plain sm_103) ----------------
__device__ __forceinline__ unsigned smem_u32(const void* p){
    unsigned a;
    asm("{ .reg .u64 t; cvta.to.shared.u64 t, %1; cvt.u32.u64 %0, t; }" : "=r"(a) : "l"(p));
    return a;
}
__device__ __forceinline__ void ldsm4(unsigned* r, unsigned addr){
    asm volatile("ldmatrix.sync.aligned.m8n8.x4.shared.b16 {%0,%1,%2,%3}, [%4];"
        : "=r"(r[0]), "=r"(r[1]), "=r"(r[2]), "=r"(r[3]) : "r"(addr));
}
__device__ __forceinline__ void mma16816(float* d, const unsigned* a, const unsigned* b){
    asm volatile(
        "mma.sync.aligned.m16n8k16.row.col.f32.bf16.bf16.f32 "
        "{%0,%1,%2,%3}, {%4,%5,%6,%7}, {%8,%9}, {%0,%1,%2,%3};"
        : "+f"(d[0]), "+f"(d[1]), "+f"(d[2]), "+f"(d[3])
        : "r"(a[0]), "r"(a[1]), "r"(a[2]), "r"(a[3]), "r"(b[0]), "r"(b[1]));
}
__device__ __forceinline__ void cpasync16(unsigned saddr, const void* g){
    asm volatile("cp.async.cg.shared.global [%0], [%1], 16;" :: "r"(saddr), "l"(g) : "memory");
}
__device__ __forceinline__ void cp_commit(){
    asm volatile("cp.async.commit_group;" ::: "memory");
}
__device__ __forceinline__ void cp_wait0(){
    asm volatile("cp.async.wait_group 0;" ::: "memory");
}

// ---------------- id dtype detection / maps ----------------
__global__ void detect_kernel(const long long* __restrict__ x){
    if (threadIdx.x == 0 && blockIdx.x == 0){
        int ok = 1;
        #pragma unroll
        for (int i = 0; i < 16; i++){
            long long v = x[i];
            if (v < 0 || v >= VOCAB) ok = 0;
        }
        g_is64 = ok;
    }
}

__global__ void build_maps(const void* __restrict__ xraw){
    int i = blockIdx.x * blockDim.x + threadIdx.x;
    if (i < 4*64) g_bar4[i] = 0u;
    if (i >= ML) return;
    int is64 = g_is64;
    int t = i >> 5, b = i & 31;
    long long id = is64 ? ((const long long*)xraw)[b*SEQL + t]
                        : (long long)((const int*)xraw)[b*SEQL + t];
    g_map1[i] = (int)id;
    int b3 = i >> 9, t3 = i & 511;
    g_map3[i] = t3*32 + b3;
}

// ---------------- fp32 -> bf16 hi/lo split conversions ----------------
// A row (K3): [hi | hi | lo], gathered rows. B row (K3): [hi | lo | hi].
__global__ void convA_kernel(const float* __restrict__ src, __nv_bfloat16* __restrict__ dst,
                             const int* __restrict__ map){
    int i = blockIdx.x * blockDim.x + threadIdx.x;   // over ML*1024
    int r = i >> 10, k = i & 1023;
    float v = src[(size_t)map[r]*HDIM + k];
    __nv_bfloat16 h = __float2bfloat16(v);
    __nv_bfloat16 l = __float2bfloat16(v - __bfloat162float(h));
    size_t base = (size_t)r * K3;
    dst[base + k] = h; dst[base + 1024 + k] = h; dst[base + 2048 + k] = l;
}
__global__ void convB_kernel(const float* __restrict__ src, __nv_bfloat16* __restrict__ dst){
    int i = blockIdx.x * blockDim.x + threadIdx.x;   // over rows*1024
    int r = i >> 10, k = i & 1023;
    float v = src[(size_t)r*HDIM + k];
    __nv_bfloat16 h = __float2bfloat16(v);
    __nv_bfloat16 l = __float2bfloat16(v - __bfloat162float(h));
    size_t base = (size_t)r * K3;
    dst[base + k] = h; dst[base + 1024 + k] = l; dst[base + 2048 + k] = h;
}

// ---------------- bf16 NT GEMM via mma.sync (HMMA) ----------------
// C[m][n] = sum_k A[bm*256+m][k] * B[bn*128+n][k], K=K3, fp32 accum.
// 256x128x64 tile, 512 threads = 16 warps (8m x 2n), warp tile 32x64,
// cp.async double buffer, XOR-swizzled 128B SMEM rows (conflict-free).
__device__ __forceinline__ unsigned sw_off(int row, int seg){
    return (unsigned)(row*128 + ((seg ^ (row & 7)) << 4));
}

extern __shared__ __align__(16) char dynsm[];
__global__ __launch_bounds__(512,1) void gemm_tc(
    const __nv_bfloat16* __restrict__ A, const __nv_bfloat16* __restrict__ B,
    float* __restrict__ C, int ldc)
{
    const int tid = threadIdx.x, wid = tid >> 5, lane = tid & 31;
    const int bn = blockIdx.x, bm = blockIdx.y;
    const unsigned sbase = smem_u32(dynsm);

    const __nv_bfloat16* Abase = A + (size_t)(bm*256)*K3;
    const __nv_bfloat16* Bbase = B + (size_t)(bn*128)*K3;

    // gmem->smem: 3072 16B-segs per stage (A rows 0..255, B rows 0..127), 6/thread
    auto issue_stage = [&](int c, int s){
        const unsigned so = sbase + (unsigned)s*STAGE_BYTES;
        #pragma unroll
        for (int i = 0; i < 6; i++){
            int idx = tid + i*512;           // 0..3071
            int row = idx >> 3, seg = idx & 7;
            if (row < 256){
                cpasync16(so + sw_off(row, seg),
                          Abase + (size_t)row*K3 + c*BK + seg*8);
            } else {
                int r = row - 256;
                cpasync16(so + 32768u + sw_off(r, seg),
                          Bbase + (size_t)r*K3 + c*BK + seg*8);
            }
        }
        cp_commit();
    };

    // warp tile: wm in {0..224 step 32} (8 m-warps), wn in {0,64}
    const int wm = (wid >> 1)*32;
    const int wn = (wid & 1)*64;
    const int g = lane >> 3, r8 = lane & 7;

    float acc[2][8][4];
    #pragma unroll
    for (int mm = 0; mm < 2; mm++)
        #pragma unroll
        for (int nn = 0; nn < 8; nn++)
            #pragma unroll
            for (int j = 0; j < 4; j++) acc[mm][nn][j] = 0.f;

    issue_stage(0, 0);

    for (int c = 0; c < KCH; c++){
        const int s = c & 1;
        cp_wait0();
        __syncthreads();
        if (c + 1 < KCH) issue_stage(c + 1, s ^ 1);

        const unsigned offA = sbase + (unsigned)s*STAGE_BYTES;
        const unsigned offB = offA + 32768u;
        #pragma unroll
        for (int ks = 0; ks < 4; ks++){
            unsigned af[2][4], bf[4][4];
            #pragma unroll
            for (int mm = 0; mm < 2; mm++){
                int row = wm + mm*16 + r8 + (g & 1)*8;
                ldsm4(af[mm], offA + sw_off(row, ks*2 + (g >> 1)));
            }
            #pragma unroll
            for (int nt = 0; nt < 4; nt++){
                int row = wn + nt*16 + r8 + (g >> 1)*8;
                ldsm4(bf[nt], offB + sw_off(row, ks*2 + (g & 1)));
            }
            #pragma unroll
            for (int mm = 0; mm < 2; mm++)
                #pragma unroll
                for (int nt = 0; nt < 4; nt++){
                    mma16816(acc[mm][2*nt],   af[mm], &bf[nt][0]);
                    mma16816(acc[mm][2*nt+1], af[mm], &bf[nt][2]);
                }
        }
        __syncthreads();
    }

    // epilogue
    const int erow = lane >> 2, ecol = (lane & 3)*2;
    #pragma unroll
    for (int mm = 0; mm < 2; mm++){
        #pragma unroll
        for (int nn = 0; nn < 8; nn++){
            size_t row = (size_t)(bm*256 + wm + mm*16 + erow);
            size_t col = (size_t)(bn*128 + wn + nn*8 + ecol);
            *(float2*)&C[row*ldc + col]       = make_float2(acc[mm][nn][0], acc[mm][nn][1]);
            *(float2*)&C[(row + 8)*ldc + col] = make_float2(acc[mm][nn][2], acc[mm][nn][3]);
        }
    }
}

// ---------------- persistent recurrent scan (unchanged) ----------------
__global__ __launch_bounds__(256,1) void scan_kernel(
    const float* __restrict__ hidden0, const float* __restrict__ W_h,
    const float* __restrict__ pre, float* __restrict__ hout)
{
    __shared__ float sh[8*HDIM];
    __shared__ float red[8*8*32];
    const int tid = threadIdx.x;
    const int bg = blockIdx.x >> 5, cg = blockIdx.x & 31;
    const int cp = tid & 31, ks = tid >> 5;
    const int col = cg*32 + cp;
    unsigned* bar = &g_bar4[bg*64];

    ulonglong2 wreg[32];
    {
        const ulonglong2* wp = (const ulonglong2*)(W_h + (size_t)col*HDIM + ks*128);
        #pragma unroll
        for (int i = 0; i < 32; i++) wreg[i] = wp[i];
    }

    const int gb = bg*8 + ks;
    const size_t ocol = (size_t)gb*HDIM + cg*32 + cp;

    for (int t = 0; t < SEQL; t++){
        const float preval = pre[(size_t)t*BATCH*HDIM + ocol];

        const float4* src = (const float4*)((t == 0)
            ? (hidden0 + (size_t)bg*8*HDIM)
            : (hout + ((size_t)(t-1)*BATCH + bg*8)*HDIM));
        float4* dst = (float4*)sh;
        #pragma unroll
        for (int i = 0; i < 8; i++) dst[tid + i*256] = src[tid + i*256];
        __syncthreads();

        u64 acc[8];
        #pragma unroll
        for (int b = 0; b < 8; b++) acc[b] = 0ull;

        const ulonglong2* hb = (const ulonglong2*)sh;
        #pragma unroll
        for (int q = 0; q < 32; q++){
            ulonglong2 w = wreg[q];
            #pragma unroll
            for (int b = 0; b < 8; b++){
                ulonglong2 h = hb[b*256 + ks*32 + q];
                acc[b] = ffma2(w.x, h.x, acc[b]);
                acc[b] = ffma2(w.y, h.y, acc[b]);
            }
        }

        #pragma unroll
        for (int b = 0; b < 8; b++){
            float2 f = unpack2(acc[b]);
            red[(ks*8 + b)*32 + cp] = f.x + f.y;
        }
        __syncthreads();

        {
            float dot = 0.f;
            #pragma unroll
            for (int k2 = 0; k2 < 8; k2++) dot += red[(k2*8 + ks)*32 + cp];
            hout[(size_t)t*BATCH*HDIM + ocol] = tanhf(dot + preval);
        }

        if (t + 1 < SEQL){
            __syncthreads();
            if (tid == 0){
                bar_arrive_release(bar);
                const unsigned target = 32u*(unsigned)(t+1);
                if (ld_acquire_gpu(bar) < target){
                    while (ld_acquire_gpu(bar) < target) __nanosleep(64);
                }
            }
            __syncthreads();
        }
    }
}

__global__ void copy_hidden(float* __restrict__ dst){
    int i = blockIdx.x * blockDim.x + threadIdx.x;
    dst[i] = g_hout[(size_t)(511*32)*HDIM + i];
}

extern "C" void kernel_launch(void* const* d_in, const int* in_sizes, int n_in,
                              void* d_out, int out_size) {
    const void*  x      = d_in[0];
    const float* hidden = (const float*)d_in[1];
    const float* emb    = (const float*)d_in[2];
    const float* W_h    = (const float*)d_in[3];
    const float* W_e    = (const float*)d_in[4];
    const float* W_o    = (const float*)d_in[5];
    float* out = (float*)d_out;

    float *pre, *hout; int *map1, *map3; __nv_bfloat16 *abig, *bo, *be;
    cudaGetSymbolAddress((void**)&pre,  g_pre);
    cudaGetSymbolAddress((void**)&hout, g_hout);
    cudaGetSymbolAddress((void**)&map1, g_map1);
    cudaGetSymbolAddress((void**)&map3, g_map3);
    cudaGetSymbolAddress((void**)&abig, g_abig);
    cudaGetSymbolAddress((void**)&bo,   g_bo);
    cudaGetSymbolAddress((void**)&be,   g_be);

    cudaFuncSetAttribute(gemm_tc, cudaFuncAttributeMaxDynamicSharedMemorySize,
                         2*STAGE_BYTES);

    detect_kernel<<<1, 32>>>((const long long*)x);
    build_maps<<<64, 256>>>(x);

    // Phase 1: pre = emb[x] @ W_e^T via HMMA (A = gathered split emb)
    convB_kernel<<<HDIM*HDIM/256, 256>>>(W_e, be);
    convA_kernel<<<ML*HDIM/256, 256>>>(emb, abig, map1);
    gemm_tc<<<dim3(8, 64), 512, 2*STAGE_BYTES>>>(abig, be, pre, HDIM);

    // Phase 2: persistent scan
    scan_kernel<<<128, 256>>>(hidden, W_h, pre, hout);

    // Phase 3: logits = outputs @ W_o^T via HMMA (A = gathered split hout)
    convB_kernel<<<VOCAB*HDIM/256, 256>>>(W_o, bo);
    convA_kernel<<<ML*HDIM/256, 256>>>(hout, abig, map3);
    gemm_tc<<<dim3(64, 64), 512, 2*STAGE_BYTES>>>(abig, bo, out, VOCAB);

    if (out_size >= LOGITS_ELEMS + BATCH*HDIM)
        copy_hidden<<<32, 1024>>>(out + LOGITS_ELEMS);
}

// round 9
// speedup vs baseline: 1.8990x; 1.0201x over previous
#include <cuda_runtime.h>
#include <cuda_bf16.h>
#include <cstdint>

typedef unsigned long long u64;

#define SEQL   512
#define BATCH  32
#define HDIM   1024
#define VOCAB  8192
#define ML     (BATCH*SEQL)              /* 16384 */
#define LOGITS_ELEMS 134217728           /* 32*512*8192 */
#define K3     3072                      /* split-K: [hi|hi|lo] x [hi|lo|hi] */
#define BK     64
#define KCH    48                        /* K3 / BK */
#define STAGE_BYTES 49152                /* (256+128)*64*2 */
#define NSTAGE 3

// ---------------- scratch (cudaMalloc forbidden) ----------------
__device__ float g_pre[ML*HDIM];                 // 64 MB, [t][b][h]
__device__ float g_hout[ML*HDIM];                // 64 MB, [t][b][h]
__device__ __nv_bfloat16 g_abig[(size_t)ML*K3];  // 96 MB: split A (phase1 then phase3)
__device__ __nv_bfloat16 g_bo[(size_t)VOCAB*K3]; // 48 MB: split W_o
__device__ __nv_bfloat16 g_be[(size_t)HDIM*K3];  //  6 MB: split W_e
__device__ int   g_map1[ML];             // row m=t*32+b -> embedding id
__device__ int   g_is64;
__device__ unsigned g_bar4[4*64];        // per-batch-group barrier counters

// ---------------- f32x2 helpers ----------------
__device__ __forceinline__ u64 ffma2(u64 a, u64 b, u64 c){
    u64 d; asm("fma.rn.f32x2 %0, %1, %2, %3;" : "=l"(d) : "l"(a), "l"(b), "l"(c)); return d;
}
__device__ __forceinline__ float2 unpack2(u64 v){
    unsigned lo, hi; asm("mov.b64 {%0, %1}, %2;" : "=r"(lo), "=r"(hi) : "l"(v));
    return make_float2(__uint_as_float(lo), __uint_as_float(hi));
}

// ---------------- barrier primitives ----------------
__device__ __forceinline__ void bar_arrive_release(unsigned* p){
    asm volatile("red.release.gpu.global.add.u32 [%0], 1;" :: "l"(p) : "memory");
}
__device__ __forceinline__ unsigned ld_acquire_gpu(const unsigned* p){
    unsigned v;
    asm volatile("ld.acquire.gpu.global.u32 %0, [%1];" : "=r"(v) : "l"(p) : "memory");
    return v;
}

// ---------------- sm80-class tensor primitives (valid on plain sm_103) ----------------
__device__ __forceinline__ unsigned smem_u32(const void* p){
    unsigned a;
    asm("{ .reg .u64 t; cvta.to.shared.u64 t, %1; cvt.u32.u64 %0, t; }" : "=r"(a) : "l"(p));
    return a;
}
__device__ __forceinline__ void ldsm4(unsigned* r, unsigned addr){
    asm volatile("ldmatrix.sync.aligned.m8n8.x4.shared.b16 {%0,%1,%2,%3}, [%4];"
        : "=r"(r[0]), "=r"(r[1]), "=r"(r[2]), "=r"(r[3]) : "r"(addr));
}
__device__ __forceinline__ void mma16816(float* d, const unsigned* a, const unsigned* b){
    asm volatile(
        "mma.sync.aligned.m16n8k16.row.col.f32.bf16.bf16.f32 "
        "{%0,%1,%2,%3}, {%4,%5,%6,%7}, {%8,%9}, {%0,%1,%2,%3};"
        : "+f"(d[0]), "+f"(d[1]), "+f"(d[2]), "+f"(d[3])
        : "r"(a[0]), "r"(a[1]), "r"(a[2]), "r"(a[3]), "r"(b[0]), "r"(b[1]));
}
__device__ __forceinline__ void cpasync16(unsigned saddr, const void* g){
    asm volatile("cp.async.cg.shared.global [%0], [%1], 16;" :: "r"(saddr), "l"(g) : "memory");
}
__device__ __forceinline__ void cp_commit(){
    asm volatile("cp.async.commit_group;" ::: "memory");
}
template<int N>
__device__ __forceinline__ void cp_wait(){
    asm volatile("cp.async.wait_group %0;" :: "n"(N) : "memory");
}

// ---------------- id dtype detection / maps ----------------
__global__ void detect_kernel(const long long* __restrict__ x){
    if (threadIdx.x == 0 && blockIdx.x == 0){
        int ok = 1;
        #pragma unroll
        for (int i = 0; i < 16; i++){
            long long v = x[i];
            if (v < 0 || v >= VOCAB) ok = 0;
        }
        g_is64 = ok;
    }
}

__global__ void build_maps(const void* __restrict__ xraw){
    int i = blockIdx.x * blockDim.x + threadIdx.x;
    if (i < 4*64) g_bar4[i] = 0u;
    if (i >= ML) return;
    int is64 = g_is64;
    int t = i >> 5, b = i & 31;
    long long id = is64 ? ((const long long*)xraw)[b*SEQL + t]
                        : (long long)((const int*)xraw)[b*SEQL + t];
    g_map1[i] = (int)id;
}

// ---------------- fp32 -> bf16 hi/lo split conversions (4 elems/thread) ----------------
__device__ __forceinline__ void split4(float4 v, uint2& uh, uint2& ul){
    __nv_bfloat16 h0 = __float2bfloat16(v.x), h1 = __float2bfloat16(v.y);
    __nv_bfloat16 h2 = __float2bfloat16(v.z), h3 = __float2bfloat16(v.w);
    __nv_bfloat16 l0 = __float2bfloat16(v.x - __bfloat162float(h0));
    __nv_bfloat16 l1 = __float2bfloat16(v.y - __bfloat162float(h1));
    __nv_bfloat16 l2 = __float2bfloat16(v.z - __bfloat162float(h2));
    __nv_bfloat16 l3 = __float2bfloat16(v.w - __bfloat162float(h3));
    __nv_bfloat162 ph0(h0, h1), ph1(h2, h3), pl0(l0, l1), pl1(l2, l3);
    uh.x = *(unsigned*)&ph0; uh.y = *(unsigned*)&ph1;
    ul.x = *(unsigned*)&pl0; ul.y = *(unsigned*)&pl1;
}
// A row (K3): [hi | hi | lo], gathered rows.
__global__ void convA_kernel(const float* __restrict__ src, __nv_bfloat16* __restrict__ dst,
                             const int* __restrict__ map){
    int i = blockIdx.x * blockDim.x + threadIdx.x;   // over ML*256
    int r = i >> 8, k4 = (i & 255) << 2;
    float4 v = *(const float4*)(src + (size_t)map[r]*HDIM + k4);
    uint2 uh, ul; split4(v, uh, ul);
    size_t base = (size_t)r * K3;
    *(uint2*)(dst + base + k4)        = uh;
    *(uint2*)(dst + base + 1024 + k4) = uh;
    *(uint2*)(dst + base + 2048 + k4) = ul;
}
// B row (K3): [hi | lo | hi]
__global__ void convB_kernel(const float* __restrict__ src, __nv_bfloat16* __restrict__ dst){
    int i = blockIdx.x * blockDim.x + threadIdx.x;   // over rows*256
    int r = i >> 8, k4 = (i & 255) << 2;
    float4 v = *(const float4*)(src + (size_t)r*HDIM + k4);
    uint2 uh, ul; split4(v, uh, ul);
    size_t base = (size_t)r * K3;
    *(uint2*)(dst + base + k4)        = uh;
    *(uint2*)(dst + base + 1024 + k4) = ul;
    *(uint2*)(dst + base + 2048 + k4) = uh;
}

// ---------------- bf16 NT GEMM via mma.sync (HMMA) ----------------
// 256x128x64 tile, 512 threads = 16 warps (8m x 2n), warp tile 32x64,
// 3-stage cp.async pipeline (wait_group 1, one sync/chunk), XOR-swizzled SMEM.
__device__ __forceinline__ unsigned sw_off(int row, int seg){
    return (unsigned)(row*128 + ((seg ^ (row & 7)) << 4));
}

extern __shared__ __align__(16) char dynsm[];
__global__ __launch_bounds__(512,1) void gemm_tc(
    const __nv_bfloat16* __restrict__ A, const __nv_bfloat16* __restrict__ B,
    float* __restrict__ C, int ldc)
{
    const int tid = threadIdx.x, wid = tid >> 5, lane = tid & 31;
    const int bn = blockIdx.x, bm = blockIdx.y;
    const unsigned sbase = smem_u32(dynsm);

    const __nv_bfloat16* Abase = A + (size_t)(bm*256)*K3;
    const __nv_bfloat16* Bbase = B + (size_t)(bn*128)*K3;

    auto issue_stage = [&](int c, int s){
        const unsigned so = sbase + (unsigned)s*STAGE_BYTES;
        #pragma unroll
        for (int i = 0; i < 6; i++){
            int idx = tid + i*512;           // 0..3071
            int row = idx >> 3, seg = idx & 7;
            if (row < 256){
                cpasync16(so + sw_off(row, seg),
                          Abase + (size_t)row*K3 + c*BK + seg*8);
            } else {
                int r = row - 256;
                cpasync16(so + 32768u + sw_off(r, seg),
                          Bbase + (size_t)r*K3 + c*BK + seg*8);
            }
        }
        cp_commit();
    };

    const int wm = (wid >> 1)*32;
    const int wn = (wid & 1)*64;
    const int g = lane >> 3, r8 = lane & 7;

    float acc[2][8][4];
    #pragma unroll
    for (int mm = 0; mm < 2; mm++)
        #pragma unroll
        for (int nn = 0; nn < 8; nn++)
            #pragma unroll
            for (int j = 0; j < 4; j++) acc[mm][nn][j] = 0.f;

    issue_stage(0, 0);
    issue_stage(1, 1);

    int s = 0;
    for (int c = 0; c < KCH; c++){
        cp_wait<1>();            // stage c resident (groups complete in order)
        __syncthreads();         // all warps done with buffer (c+2)%3 from iter c-1
        if (c + 2 < KCH) issue_stage(c + 2, (c + 2) % NSTAGE);

        const unsigned offA = sbase + (unsigned)s*STAGE_BYTES;
        const unsigned offB = offA + 32768u;
        #pragma unroll
        for (int ks = 0; ks < 4; ks++){
            unsigned af[2][4], bf[4][4];
            #pragma unroll
            for (int mm = 0; mm < 2; mm++){
                int row = wm + mm*16 + r8 + (g & 1)*8;
                ldsm4(af[mm], offA + sw_off(row, ks*2 + (g >> 1)));
            }
            #pragma unroll
            for (int nt = 0; nt < 4; nt++){
                int row = wn + nt*16 + r8 + (g >> 1)*8;
                ldsm4(bf[nt], offB + sw_off(row, ks*2 + (g & 1)));
            }
            #pragma unroll
            for (int mm = 0; mm < 2; mm++)
                #pragma unroll
                for (int nt = 0; nt < 4; nt++){
                    mma16816(acc[mm][2*nt],   af[mm], &bf[nt][0]);
                    mma16816(acc[mm][2*nt+1], af[mm], &bf[nt][2]);
                }
        }
        s = (s + 1 == NSTAGE) ? 0 : s + 1;
    }

    const int erow = lane >> 2, ecol = (lane & 3)*2;
    #pragma unroll
    for (int mm = 0; mm < 2; mm++){
        #pragma unroll
        for (int nn = 0; nn < 8; nn++){
            size_t row = (size_t)(bm*256 + wm + mm*16 + erow);
            size_t col = (size_t)(bn*128 + wn + nn*8 + ecol);
            *(float2*)&C[row*ldc + col]       = make_float2(acc[mm][nn][0], acc[mm][nn][1]);
            *(float2*)&C[(row + 8)*ldc + col] = make_float2(acc[mm][nn][2], acc[mm][nn][3]);
        }
    }
}

// ---------------- persistent recurrent scan ----------------
// Same proven structure; epilogue now ALSO emits the split-bf16 logits-A row
// (b*512+t) directly, deleting the phase-3 convA pass entirely.
__global__ __launch_bounds__(256,1) void scan_kernel(
    const float* __restrict__ hidden0, const float* __restrict__ W_h,
    const float* __restrict__ pre, float* __restrict__ hout,
    __nv_bfloat16* __restrict__ abig)
{
    __shared__ float sh[8*HDIM];
    __shared__ float red[8*8*32];
    const int tid = threadIdx.x;
    const int bg = blockIdx.x >> 5, cg = blockIdx.x & 31;
    const int cp = tid & 31, ks = tid >> 5;
    const int col = cg*32 + cp;
    unsigned* bar = &g_bar4[bg*64];

    ulonglong2 wreg[32];
    {
        const ulonglong2* wp = (const ulonglong2*)(W_h + (size_t)col*HDIM + ks*128);
        #pragma unroll
        for (int i = 0; i < 32; i++) wreg[i] = wp[i];
    }

    const int gb = bg*8 + ks;                      // this thread's batch
    const int oc = cg*32 + cp;                     // this thread's column
    const size_t ocol = (size_t)gb*HDIM + oc;

    for (int t = 0; t < SEQL; t++){
        const float preval = pre[(size_t)t*BATCH*HDIM + ocol];

        const float4* src = (const float4*)((t == 0)
            ? (hidden0 + (size_t)bg*8*HDIM)
            : (hout + ((size_t)(t-1)*BATCH + bg*8)*HDIM));
        float4* dst = (float4*)sh;
        #pragma unroll
        for (int i = 0; i < 8; i++) dst[tid + i*256] = src[tid + i*256];
        __syncthreads();

        u64 acc[8];
        #pragma unroll
        for (int b = 0; b < 8; b++) acc[b] = 0ull;

        const ulonglong2* hb = (const ulonglong2*)sh;
        #pragma unroll
        for (int q = 0; q < 32; q++){
            ulonglong2 w = wreg[q];
            #pragma unroll
            for (int b = 0; b < 8; b++){
                ulonglong2 h = hb[b*256 + ks*32 + q];
                acc[b] = ffma2(w.x, h.x, acc[b]);
                acc[b] = ffma2(w.y, h.y, acc[b]);
            }
        }

        #pragma unroll
        for (int b = 0; b < 8; b++){
            float2 f = unpack2(acc[b]);
            red[(ks*8 + b)*32 + cp] = f.x + f.y;
        }
        __syncthreads();

        {
            float dot = 0.f;
            #pragma unroll
            for (int k2 = 0; k2 < 8; k2++) dot += red[(k2*8 + ks)*32 + cp];
            float hval = tanhf(dot + preval);
            hout[(size_t)t*BATCH*HDIM + ocol] = hval;
            // fused split-bf16 write of logits-GEMM A row m = gb*512 + t
            __nv_bfloat16 hh = __float2bfloat16(hval);
            __nv_bfloat16 hl = __float2bfloat16(hval - __bfloat162float(hh));
            size_t arow = (size_t)(gb*SEQL + t) * K3;
            abig[arow + oc]        = hh;
            abig[arow + 1024 + oc] = hh;
            abig[arow + 2048 + oc] = hl;
        }

        if (t + 1 < SEQL){
            __syncthreads();
            if (tid == 0){
                bar_arrive_release(bar);
                const unsigned target = 32u*(unsigned)(t+1);
                if (ld_acquire_gpu(bar) < target){
                    while (ld_acquire_gpu(bar) < target) __nanosleep(64);
                }
            }
            __syncthreads();
        }
    }
}

__global__ void copy_hidden(float* __restrict__ dst){
    int i = blockIdx.x * blockDim.x + threadIdx.x;
    dst[i] = g_hout[(size_t)(511*32)*HDIM + i];
}

extern "C" void kernel_launch(void* const* d_in, const int* in_sizes, int n_in,
                              void* d_out, int out_size) {
    const void*  x      = d_in[0];
    const float* hidden = (const float*)d_in[1];
    const float* emb    = (const float*)d_in[2];
    const float* W_h    = (const float*)d_in[3];
    const float* W_e    = (const float*)d_in[4];
    const float* W_o    = (const float*)d_in[5];
    float* out = (float*)d_out;

    float *pre, *hout; int *map1; __nv_bfloat16 *abig, *bo, *be;
    cudaGetSymbolAddress((void**)&pre,  g_pre);
    cudaGetSymbolAddress((void**)&hout, g_hout);
    cudaGetSymbolAddress((void**)&map1, g_map1);
    cudaGetSymbolAddress((void**)&abig, g_abig);
    cudaGetSymbolAddress((void**)&bo,   g_bo);
    cudaGetSymbolAddress((void**)&be,   g_be);

    cudaFuncSetAttribute(gemm_tc, cudaFuncAttributeMaxDynamicSharedMemorySize,
                         NSTAGE*STAGE_BYTES);

    detect_kernel<<<1, 32>>>((const long long*)x);
    build_maps<<<64, 256>>>(x);

    // Phase 1: pre = emb[x] @ W_e^T via HMMA (A = gathered split emb)
    convB_kernel<<<HDIM, 256>>>(W_e, be);
    convA_kernel<<<ML, 256>>>(emb, abig, map1);
    gemm_tc<<<dim3(8, 64), 512, NSTAGE*STAGE_BYTES>>>(abig, be, pre, HDIM);

    // W_o split (independent of scan) before the scan
    convB_kernel<<<VOCAB, 256>>>(W_o, bo);

    // Phase 2: persistent scan; emits split-A for phase 3 directly
    scan_kernel<<<128, 256>>>(hidden, W_h, pre, hout, abig);

    // Phase 3: logits = outputs @ W_o^T via HMMA
    gemm_tc<<<dim3(64, 64), 512, NSTAGE*STAGE_BYTES>>>(abig, bo, out, VOCAB);

    if (out_size >= LOGITS_ELEMS + BATCH*HDIM)
        copy_hidden<<<32, 1024>>>(out + LOGITS_ELEMS);
}

// round 10
// speedup vs baseline: 2.2762x; 1.1986x over previous
#include <cuda_runtime.h>
#include <cuda_bf16.h>
#include <cuda_fp16.h>
#include <cstdint>

typedef unsigned long long u64;

#define SEQL   512
#define BATCH  32
#define HDIM   1024
#define VOCAB  8192
#define ML     (BATCH*SEQL)              /* 16384 */
#define LOGITS_ELEMS 134217728           /* 32*512*8192 */
#define K2     2048                      /* fp16 A-split: [Ah|Al] x [Bh wrap] */
#define BK     64
#define KCH    32                        /* K2 / BK */
#define STAGE_BYTES 49152                /* (256+128)*64*2 */
#define NSTAGE 3

// ---------------- scratch (cudaMalloc forbidden) ----------------
__device__ float g_pre[ML*HDIM];                 // 64 MB, [t][b][h]
__device__ float g_hout[ML*HDIM];                // 64 MB, [t][b][h]
__device__ __half g_a2[(size_t)ML*K2];           // 64 MB: fp16 [Ah|Al] rows
__device__ __half g_bo[(size_t)VOCAB*HDIM];      // 16 MB: fp16 W_o (hi only)
__device__ __half g_be[(size_t)HDIM*HDIM];       //  2 MB: fp16 W_e (hi only)
__device__ int   g_map1[ML];             // row m=t*32+b -> embedding id
__device__ int   g_is64;
__device__ unsigned g_bar4[4*64];        // per-batch-group barrier counters

// ---------------- f32x2 helpers ----------------
__device__ __forceinline__ u64 ffma2(u64 a, u64 b, u64 c){
    u64 d; asm("fma.rn.f32x2 %0, %1, %2, %3;" : "=l"(d) : "l"(a), "l"(b), "l"(c)); return d;
}
__device__ __forceinline__ float2 unpack2(u64 v){
    unsigned lo, hi; asm("mov.b64 {%0, %1}, %2;" : "=r"(lo), "=r"(hi) : "l"(v));
    return make_float2(__uint_as_float(lo), __uint_as_float(hi));
}

// ---------------- barrier primitives ----------------
__device__ __forceinline__ void bar_arrive_release(unsigned* p){
    asm volatile("red.release.gpu.global.add.u32 [%0], 1;" :: "l"(p) : "memory");
}
__device__ __forceinline__ unsigned ld_acquire_gpu(const unsigned* p){
    unsigned v;
    asm volatile("ld.acquire.gpu.global.u32 %0, [%1];" : "=r"(v) : "l"(p) : "memory");
    return v;
}

// ---------------- sm80-class tensor primitives (valid on plain sm_103) ----------------
__device__ __forceinline__ unsigned smem_u32(const void* p){
    unsigned a;
    asm("{ .reg .u64 t; cvta.to.shared.u64 t, %1; cvt.u32.u64 %0, t; }" : "=r"(a) : "l"(p));
    return a;
}
__device__ __forceinline__ void ldsm4(unsigned* r, unsigned addr){
    asm volatile("ldmatrix.sync.aligned.m8n8.x4.shared.b16 {%0,%1,%2,%3}, [%4];"
        : "=r"(r[0]), "=r"(r[1]), "=r"(r[2]), "=r"(r[3]) : "r"(addr));
}
__device__ __forceinline__ void mma16816h(float* d, const unsigned* a, const unsigned* b){
    asm volatile(
        "mma.sync.aligned.m16n8k16.row.col.f32.f16.f16.f32 "
        "{%0,%1,%2,%3}, {%4,%5,%6,%7}, {%8,%9}, {%0,%1,%2,%3};"
        : "+f"(d[0]), "+f"(d[1]), "+f"(d[2]), "+f"(d[3])
        : "r"(a[0]), "r"(a[1]), "r"(a[2]), "r"(a[3]), "r"(b[0]), "r"(b[1]));
}
__device__ __forceinline__ void cpasync16(unsigned saddr, const void* g){
    asm volatile("cp.async.cg.shared.global [%0], [%1], 16;" :: "r"(saddr), "l"(g) : "memory");
}
__device__ __forceinline__ void cp_commit(){
    asm volatile("cp.async.commit_group;" ::: "memory");
}
template<int N>
__device__ __forceinline__ void cp_wait(){
    asm volatile("cp.async.wait_group %0;" :: "n"(N) : "memory");
}

// ---------------- id dtype detection / maps ----------------
__global__ void detect_kernel(const long long* __restrict__ x){
    if (threadIdx.x == 0 && blockIdx.x == 0){
        int ok = 1;
        #pragma unroll
        for (int i = 0; i < 16; i++){
            long long v = x[i];
            if (v < 0 || v >= VOCAB) ok = 0;
        }
        g_is64 = ok;
    }
}

__global__ void build_maps(const void* __restrict__ xraw){
    int i = blockIdx.x * blockDim.x + threadIdx.x;
    if (i < 4*64) g_bar4[i] = 0u;
    if (i >= ML) return;
    int is64 = g_is64;
    int t = i >> 5, b = i & 31;
    long long id = is64 ? ((const long long*)xraw)[b*SEQL + t]
                        : (long long)((const int*)xraw)[b*SEQL + t];
    g_map1[i] = (int)id;
}

// ---------------- fp32 -> fp16 conversions ----------------
__device__ __forceinline__ void split4h(float4 v, uint2& uh, uint2& ul){
    __half h0 = __float2half(v.x), h1 = __float2half(v.y);
    __half h2 = __float2half(v.z), h3 = __float2half(v.w);
    __half l0 = __float2half(v.x - __half2float(h0));
    __half l1 = __float2half(v.y - __half2float(h1));
    __half l2 = __float2half(v.z - __half2float(h2));
    __half l3 = __float2half(v.w - __half2float(h3));
    __half2 p0(h0, h1), p1(h2, h3), q0(l0, l1), q1(l2, l3);
    uh.x = *(unsigned*)&p0; uh.y = *(unsigned*)&p1;
    ul.x = *(unsigned*)&q0; ul.y = *(unsigned*)&q1;
}
// A rows (K2): [Ah | Al], gathered via map.
__global__ void convA_kernel(const float* __restrict__ src, __half* __restrict__ dst,
                             const int* __restrict__ map){
    int i = blockIdx.x * blockDim.x + threadIdx.x;   // over ML*256
    int r = i >> 8, k4 = (i & 255) << 2;
    float4 v = *(const float4*)(src + (size_t)map[r]*HDIM + k4);
    uint2 uh, ul; split4h(v, uh, ul);
    size_t base = (size_t)r * K2;
    *(uint2*)(dst + base + k4)        = uh;
    *(uint2*)(dst + base + 1024 + k4) = ul;
}
// B: plain fp16 downcast (hi only; GEMM re-reads the same copy for both halves).
__global__ void convB_kernel(const float* __restrict__ src, __half* __restrict__ dst){
    int i = blockIdx.x * blockDim.x + threadIdx.x;   // over rows*256
    int r = i >> 8, k4 = (i & 255) << 2;
    float4 v = *(const float4*)(src + (size_t)r*HDIM + k4);
    __half2 p0(__float2half(v.x), __float2half(v.y));
    __half2 p1(__float2half(v.z), __float2half(v.w));
    uint2 uh; uh.x = *(unsigned*)&p0; uh.y = *(unsigned*)&p1;
    *(uint2*)(dst + (size_t)r*HDIM + k4) = uh;
}

// ---------------- fp16 NT GEMM via mma.sync (HMMA) ----------------
// C[m][n] = sum_{k<K2} A[bm*256+m][k] * B[bn*128+n][(k mod 1024)], fp32 accum.
// A rows are 2048 fp16 ([Ah|Al]); B rows are 1024 fp16 (read twice -> (Ah+Al)·Bh).
// 256x128x64 tile, 512 threads, 3-stage cp.async, XOR-swizzled SMEM.
__device__ __forceinline__ unsigned sw_off(int row, int seg){
    return (unsigned)(row*128 + ((seg ^ (row & 7)) << 4));
}

extern __shared__ __align__(16) char dynsm[];
__global__ __launch_bounds__(512,1) void gemm_tc(
    const __half* __restrict__ A, const __half* __restrict__ B,
    float* __restrict__ C, int ldc)
{
    const int tid = threadIdx.x, wid = tid >> 5, lane = tid & 31;
    const int bn = blockIdx.x, bm = blockIdx.y;
    const unsigned sbase = smem_u32(dynsm);

    const __half* Abase = A + (size_t)(bm*256)*K2;
    const __half* Bbase = B + (size_t)(bn*128)*HDIM;

    auto issue_stage = [&](int c, int s){
        const unsigned so = sbase + (unsigned)s*STAGE_BYTES;
        const int ak = c*BK;
        const int bk = (c & 15)*BK;
        #pragma unroll
        for (int i = 0; i < 6; i++){
            int idx = tid + i*512;           // 0..3071
            int row = idx >> 3, seg = idx & 7;
            if (row < 256){
                cpasync16(so + sw_off(row, seg),
                          Abase + (size_t)row*K2 + ak + seg*8);
            } else {
                int r = row - 256;
                cpasync16(so + 32768u + sw_off(r, seg),
                          Bbase + (size_t)r*HDIM + bk + seg*8);
            }
        }
        cp_commit();
    };

    const int wm = (wid >> 1)*32;
    const int wn = (wid & 1)*64;
    const int g = lane >> 3, r8 = lane & 7;

    float acc[2][8][4];
    #pragma unroll
    for (int mm = 0; mm < 2; mm++)
        #pragma unroll
        for (int nn = 0; nn < 8; nn++)
            #pragma unroll
            for (int j = 0; j < 4; j++) acc[mm][nn][j] = 0.f;

    issue_stage(0, 0);
    issue_stage(1, 1);

    int s = 0;
    for (int c = 0; c < KCH; c++){
        cp_wait<1>();
        __syncthreads();
        if (c + 2 < KCH) issue_stage(c + 2, (c + 2) % NSTAGE);

        const unsigned offA = sbase + (unsigned)s*STAGE_BYTES;
        const unsigned offB = offA + 32768u;
        #pragma unroll
        for (int ks = 0; ks < 4; ks++){
            unsigned af[2][4], bf[4][4];
            #pragma unroll
            for (int mm = 0; mm < 2; mm++){
                int row = wm + mm*16 + r8 + (g & 1)*8;
                ldsm4(af[mm], offA + sw_off(row, ks*2 + (g >> 1)));
            }
            #pragma unroll
            for (int nt = 0; nt < 4; nt++){
                int row = wn + nt*16 + r8 + (g >> 1)*8;
                ldsm4(bf[nt], offB + sw_off(row, ks*2 + (g & 1)));
            }
            #pragma unroll
            for (int mm = 0; mm < 2; mm++)
                #pragma unroll
                for (int nt = 0; nt < 4; nt++){
                    mma16816h(acc[mm][2*nt],   af[mm], &bf[nt][0]);
                    mma16816h(acc[mm][2*nt+1], af[mm], &bf[nt][2]);
                }
        }
        s = (s + 1 == NSTAGE) ? 0 : s + 1;
    }

    const int erow = lane >> 2, ecol = (lane & 3)*2;
    #pragma unroll
    for (int mm = 0; mm < 2; mm++){
        #pragma unroll
        for (int nn = 0; nn < 8; nn++){
            size_t row = (size_t)(bm*256 + wm + mm*16 + erow);
            size_t col = (size_t)(bn*128 + wn + nn*8 + ecol);
            *(float2*)&C[row*ldc + col]       = make_float2(acc[mm][nn][0], acc[mm][nn][1]);
            *(float2*)&C[(row + 8)*ldc + col] = make_float2(acc[mm][nn][2], acc[mm][nn][3]);
        }
    }
}

// ---------------- persistent recurrent scan ----------------
// Proven structure; epilogue emits the fp16 [Ah|Al] logits-A row (b*512+t).
__global__ __launch_bounds__(256,1) void scan_kernel(
    const float* __restrict__ hidden0, const float* __restrict__ W_h,
    const float* __restrict__ pre, float* __restrict__ hout,
    __half* __restrict__ a2)
{
    __shared__ float sh[8*HDIM];
    __shared__ float red[8*8*32];
    const int tid = threadIdx.x;
    const int bg = blockIdx.x >> 5, cg = blockIdx.x & 31;
    const int cp = tid & 31, ks = tid >> 5;
    const int col = cg*32 + cp;
    unsigned* bar = &g_bar4[bg*64];

    ulonglong2 wreg[32];
    {
        const ulonglong2* wp = (const ulonglong2*)(W_h + (size_t)col*HDIM + ks*128);
        #pragma unroll
        for (int i = 0; i < 32; i++) wreg[i] = wp[i];
    }

    const int gb = bg*8 + ks;
    const int oc = cg*32 + cp;
    const size_t ocol = (size_t)gb*HDIM + oc;

    for (int t = 0; t < SEQL; t++){
        const float preval = pre[(size_t)t*BATCH*HDIM + ocol];

        const float4* src = (const float4*)((t == 0)
            ? (hidden0 + (size_t)bg*8*HDIM)
            : (hout + ((size_t)(t-1)*BATCH + bg*8)*HDIM));
        float4* dst = (float4*)sh;
        #pragma unroll
        for (int i = 0; i < 8; i++) dst[tid + i*256] = src[tid + i*256];
        __syncthreads();

        u64 acc[8];
        #pragma unroll
        for (int b = 0; b < 8; b++) acc[b] = 0ull;

        const ulonglong2* hb = (const ulonglong2*)sh;
        #pragma unroll
        for (int q = 0; q < 32; q++){
            ulonglong2 w = wreg[q];
            #pragma unroll
            for (int b = 0; b < 8; b++){
                ulonglong2 h = hb[b*256 + ks*32 + q];
                acc[b] = ffma2(w.x, h.x, acc[b]);
                acc[b] = ffma2(w.y, h.y, acc[b]);
            }
        }

        #pragma unroll
        for (int b = 0; b < 8; b++){
            float2 f = unpack2(acc[b]);
            red[(ks*8 + b)*32 + cp] = f.x + f.y;
        }
        __syncthreads();

        {
            float dot = 0.f;
            #pragma unroll
            for (int k2 = 0; k2 < 8; k2++) dot += red[(k2*8 + ks)*32 + cp];
            float hval = tanhf(dot + preval);
            hout[(size_t)t*BATCH*HDIM + ocol] = hval;
            // fused fp16 [Ah|Al] write of logits-GEMM A row m = gb*512 + t
            __half hh = __float2half(hval);
            __half hl = __float2half(hval - __half2float(hh));
            size_t arow = (size_t)(gb*SEQL + t) * K2;
            a2[arow + oc]        = hh;
            a2[arow + 1024 + oc] = hl;
        }

        if (t + 1 < SEQL){
            __syncthreads();
            if (tid == 0){
                bar_arrive_release(bar);
                const unsigned target = 32u*(unsigned)(t+1);
                if (ld_acquire_gpu(bar) < target){
                    while (ld_acquire_gpu(bar) < target) __nanosleep(64);
                }
            }
            __syncthreads();
        }
    }
}

__global__ void copy_hidden(float* __restrict__ dst){
    int i = blockIdx.x * blockDim.x + threadIdx.x;
    dst[i] = g_hout[(size_t)(511*32)*HDIM + i];
}

extern "C" void kernel_launch(void* const* d_in, const int* in_sizes, int n_in,
                              void* d_out, int out_size) {
    const void*  x      = d_in[0];
    const float* hidden = (const float*)d_in[1];
    const float* emb    = (const float*)d_in[2];
    const float* W_h    = (const float*)d_in[3];
    const float* W_e    = (const float*)d_in[4];
    const float* W_o    = (const float*)d_in[5];
    float* out = (float*)d_out;

    float *pre, *hout; int *map1; __half *a2, *bo, *be;
    cudaGetSymbolAddress((void**)&pre,  g_pre);
    cudaGetSymbolAddress((void**)&hout, g_hout);
    cudaGetSymbolAddress((void**)&map1, g_map1);
    cudaGetSymbolAddress((void**)&a2,   g_a2);
    cudaGetSymbolAddress((void**)&bo,   g_bo);
    cudaGetSymbolAddress((void**)&be,   g_be);

    cudaFuncSetAttribute(gemm_tc, cudaFuncAttributeMaxDynamicSharedMemorySize,
                         NSTAGE*STAGE_BYTES);

    detect_kernel<<<1, 32>>>((const long long*)x);
    build_maps<<<64, 256>>>(x);

    // Phase 1: pre = emb[x] @ W_e^T via fp16 HMMA (A = gathered [Ah|Al])
    convB_kernel<<<HDIM, 256>>>(W_e, be);
    convA_kernel<<<ML, 256>>>(emb, a2, map1);
    gemm_tc<<<dim3(8, 64), 512, NSTAGE*STAGE_BYTES>>>(a2, be, pre, HDIM);

    // W_o downcast (independent of scan) before the scan
    convB_kernel<<<VOCAB, 256>>>(W_o, bo);

    // Phase 2: persistent scan; emits fp16 split-A for phase 3 directly
    scan_kernel<<<128, 256>>>(hidden, W_h, pre, hout, a2);

    // Phase 3: logits = outputs @ W_o^T via fp16 HMMA
    gemm_tc<<<dim3(64, 64), 512, NSTAGE*STAGE_BYTES>>>(a2, bo, out, VOCAB);

    if (out_size >= LOGITS_ELEMS + BATCH*HDIM)
        copy_hidden<<<32, 1024>>>(out + LOGITS_ELEMS);
}

// round 11
// speedup vs baseline: 2.9264x; 1.2856x over previous
#include <cuda_runtime.h>
#include <cuda_bf16.h>
#include <cuda_fp16.h>
#include <cstdint>

typedef unsigned long long u64;

#define SEQL   512
#define BATCH  32
#define HDIM   1024
#define VOCAB  8192
#define ML     (BATCH*SEQL)              /* 16384 */
#define LOGITS_ELEMS 134217728           /* 32*512*8192 */
#define K2     2048                      /* fp16 A-split: [Ah|Al] x [Bh wrap] */
#define BK     64
#define KCH    32                        /* K2 / BK */
#define STAGE_BYTES 49152                /* (256+128)*64*2 */
#define NSTAGE 3
#define WSTRIDE 1032                     /* scan smem row: 1024 halfs + 8 pad */
#define WROWB   2064                     /* bytes per scan smem row */
#define SCAN_SMEM 66048                  /* 32 rows * 2064 B */

// ---------------- scratch (cudaMalloc forbidden) ----------------
__device__ float g_pre[ML*HDIM];                 // 64 MB, [t][b][h]
__device__ float g_hout[ML*HDIM];                // 64 MB, [t][b][h] (only t=511 used)
__device__ __half g_a2[(size_t)ML*K2];           // 64 MB: fp16 [Ah|Al] rows
__device__ __half g_bo[(size_t)VOCAB*HDIM];      // 16 MB: fp16 W_o (hi only)
__device__ __half g_be[(size_t)HDIM*HDIM];       //  2 MB: fp16 W_e (hi only)
__device__ __half g_h0[BATCH*K2];                // 128 KB: initial hidden [hi|lo]
__device__ int   g_map1[ML];             // row m=t*32+b -> embedding id
__device__ int   g_is64;
__device__ unsigned g_bar4[4*64];        // per-batch-group barrier counters

// ---------------- barrier primitives ----------------
__device__ __forceinline__ void bar_arrive_release(unsigned* p){
    asm volatile("red.release.gpu.global.add.u32 [%0], 1;" :: "l"(p) : "memory");
}
__device__ __forceinline__ unsigned ld_acquire_gpu(const unsigned* p){
    unsigned v;
    asm volatile("ld.acquire.gpu.global.u32 %0, [%1];" : "=r"(v) : "l"(p) : "memory");
    return v;
}

// ---------------- sm80-class tensor primitives (valid on plain sm_103) ----------------
__device__ __forceinline__ unsigned smem_u32(const void* p){
    unsigned a;
    asm("{ .reg .u64 t; cvta.to.shared.u64 t, %1; cvt.u32.u64 %0, t; }" : "=r"(a) : "l"(p));
    return a;
}
__device__ __forceinline__ void ldsm4(unsigned* r, unsigned addr){
    asm volatile("ldmatrix.sync.aligned.m8n8.x4.shared.b16 {%0,%1,%2,%3}, [%4];"
        : "=r"(r[0]), "=r"(r[1]), "=r"(r[2]), "=r"(r[3]) : "r"(addr));
}
__device__ __forceinline__ void mma16816h(float* d, const unsigned* a, const unsigned* b){
    asm volatile(
        "mma.sync.aligned.m16n8k16.row.col.f32.f16.f16.f32 "
        "{%0,%1,%2,%3}, {%4,%5,%6,%7}, {%8,%9}, {%0,%1,%2,%3};"
        : "+f"(d[0]), "+f"(d[1]), "+f"(d[2]), "+f"(d[3])
        : "r"(a[0]), "r"(a[1]), "r"(a[2]), "r"(a[3]), "r"(b[0]), "r"(b[1]));
}
__device__ __forceinline__ void cpasync16(unsigned saddr, const void* g){
    asm volatile("cp.async.cg.shared.global [%0], [%1], 16;" :: "r"(saddr), "l"(g) : "memory");
}
__device__ __forceinline__ void cp_commit(){
    asm volatile("cp.async.commit_group;" ::: "memory");
}
template<int N>
__device__ __forceinline__ void cp_wait(){
    asm volatile("cp.async.wait_group %0;" :: "n"(N) : "memory");
}

// ---------------- id dtype detection / maps ----------------
__global__ void detect_kernel(const long long* __restrict__ x){
    if (threadIdx.x == 0 && blockIdx.x == 0){
        int ok = 1;
        #pragma unroll
        for (int i = 0; i < 16; i++){
            long long v = x[i];
            if (v < 0 || v >= VOCAB) ok = 0;
        }
        g_is64 = ok;
    }
}

__global__ void build_maps(const void* __restrict__ xraw){
    int i = blockIdx.x * blockDim.x + threadIdx.x;
    if (i < 4*64) g_bar4[i] = 0u;
    if (i >= ML) return;
    int is64 = g_is64;
    int t = i >> 5, b = i & 31;
    long long id = is64 ? ((const long long*)xraw)[b*SEQL + t]
                        : (long long)((const int*)xraw)[b*SEQL + t];
    g_map1[i] = (int)id;
}

// ---------------- fp32 -> fp16 conversions ----------------
__device__ __forceinline__ void split4h(float4 v, uint2& uh, uint2& ul){
    __half h0 = __float2half(v.x), h1 = __float2half(v.y);
    __half h2 = __float2half(v.z), h3 = __float2half(v.w);
    __half l0 = __float2half(v.x - __half2float(h0));
    __half l1 = __float2half(v.y - __half2float(h1));
    __half l2 = __float2half(v.z - __half2float(h2));
    __half l3 = __float2half(v.w - __half2float(h3));
    __half2 p0(h0, h1), p1(h2, h3), q0(l0, l1), q1(l2, l3);
    uh.x = *(unsigned*)&p0; uh.y = *(unsigned*)&p1;
    ul.x = *(unsigned*)&q0; ul.y = *(unsigned*)&q1;
}
// A rows (K2): [Ah | Al], gathered via map.
__global__ void convA_kernel(const float* __restrict__ src, __half* __restrict__ dst,
                             const int* __restrict__ map){
    int i = blockIdx.x * blockDim.x + threadIdx.x;   // over ML*256
    int r = i >> 8, k4 = (i & 255) << 2;
    float4 v = *(const float4*)(src + (size_t)map[r]*HDIM + k4);
    uint2 uh, ul; split4h(v, uh, ul);
    size_t base = (size_t)r * K2;
    *(uint2*)(dst + base + k4)        = uh;
    *(uint2*)(dst + base + 1024 + k4) = ul;
}
// B: plain fp16 downcast (hi only; GEMM re-reads the same copy for both halves).
__global__ void convB_kernel(const float* __restrict__ src, __half* __restrict__ dst){
    int i = blockIdx.x * blockDim.x + threadIdx.x;   // over rows*256
    int r = i >> 8, k4 = (i & 255) << 2;
    float4 v = *(const float4*)(src + (size_t)r*HDIM + k4);
    __half2 p0(__float2half(v.x), __float2half(v.y));
    __half2 p1(__float2half(v.z), __float2half(v.w));
    uint2 uh; uh.x = *(unsigned*)&p0; uh.y = *(unsigned*)&p1;
    *(uint2*)(dst + (size_t)r*HDIM + k4) = uh;
}
// initial hidden -> [hi|lo] fp16 rows (same format as a2 rows)
__global__ void convH0_kernel(const float* __restrict__ hidden, __half* __restrict__ h0){
    int i = blockIdx.x * blockDim.x + threadIdx.x;   // 32*256
    int b = i >> 8, k4 = (i & 255) << 2;
    float4 v = *(const float4*)(hidden + (size_t)b*HDIM + k4);
    uint2 uh, ul; split4h(v, uh, ul);
    *(uint2*)(h0 + (size_t)b*K2 + k4)        = uh;
    *(uint2*)(h0 + (size_t)b*K2 + 1024 + k4) = ul;
}

// ---------------- fp16 NT GEMM via mma.sync (HMMA) ----------------
__device__ __forceinline__ unsigned sw_off(int row, int seg){
    return (unsigned)(row*128 + ((seg ^ (row & 7)) << 4));
}

extern __shared__ __align__(16) char dynsm[];
__global__ __launch_bounds__(512,1) void gemm_tc(
    const __half* __restrict__ A, const __half* __restrict__ B,
    float* __restrict__ C, int ldc)
{
    const int tid = threadIdx.x, wid = tid >> 5, lane = tid & 31;
    const int bn = blockIdx.x, bm = blockIdx.y;
    const unsigned sbase = smem_u32(dynsm);

    const __half* Abase = A + (size_t)(bm*256)*K2;
    const __half* Bbase = B + (size_t)(bn*128)*HDIM;

    auto issue_stage = [&](int c, int s){
        const unsigned so = sbase + (unsigned)s*STAGE_BYTES;
        const int ak = c*BK;
        const int bk = (c & 15)*BK;
        #pragma unroll
        for (int i = 0; i < 6; i++){
            int idx = tid + i*512;
            int row = idx >> 3, seg = idx & 7;
            if (row < 256){
                cpasync16(so + sw_off(row, seg),
                          Abase + (size_t)row*K2 + ak + seg*8);
            } else {
                int r = row - 256;
                cpasync16(so + 32768u + sw_off(r, seg),
                          Bbase + (size_t)r*HDIM + bk + seg*8);
            }
        }
        cp_commit();
    };

    const int wm = (wid >> 1)*32;
    const int wn = (wid & 1)*64;
    const int g = lane >> 3, r8 = lane & 7;

    float acc[2][8][4];
    #pragma unroll
    for (int mm = 0; mm < 2; mm++)
        #pragma unroll
        for (int nn = 0; nn < 8; nn++)
            #pragma unroll
            for (int j = 0; j < 4; j++) acc[mm][nn][j] = 0.f;

    issue_stage(0, 0);
    issue_stage(1, 1);

    int s = 0;
    for (int c = 0; c < KCH; c++){
        cp_wait<1>();
        __syncthreads();
        if (c + 2 < KCH) issue_stage(c + 2, (c + 2) % NSTAGE);

        const unsigned offA = sbase + (unsigned)s*STAGE_BYTES;
        const unsigned offB = offA + 32768u;
        #pragma unroll
        for (int ks = 0; ks < 4; ks++){
            unsigned af[2][4], bf[4][4];
            #pragma unroll
            for (int mm = 0; mm < 2; mm++){
                int row = wm + mm*16 + r8 + (g & 1)*8;
                ldsm4(af[mm], offA + sw_off(row, ks*2 + (g >> 1)));
            }
            #pragma unroll
            for (int nt = 0; nt < 4; nt++){
                int row = wn + nt*16 + r8 + (g >> 1)*8;
                ldsm4(bf[nt], offB + sw_off(row, ks*2 + (g & 1)));
            }
            #pragma unroll
            for (int mm = 0; mm < 2; mm++)
                #pragma unroll
                for (int nt = 0; nt < 4; nt++){
                    mma16816h(acc[mm][2*nt],   af[mm], &bf[nt][0]);
                    mma16816h(acc[mm][2*nt+1], af[mm], &bf[nt][2]);
                }
        }
        s = (s + 1 == NSTAGE) ? 0 : s + 1;
    }

    const int erow = lane >> 2, ecol = (lane & 3)*2;
    #pragma unroll
    for (int mm = 0; mm < 2; mm++){
        #pragma unroll
        for (int nn = 0; nn < 8; nn++){
            size_t row = (size_t)(bm*256 + wm + mm*16 + erow);
            size_t col = (size_t)(bn*128 + wn + nn*8 + ecol);
            *(float2*)&C[row*ldc + col]       = make_float2(acc[mm][nn][0], acc[mm][nn][1]);
            *(float2*)&C[(row + 8)*ldc + col] = make_float2(acc[mm][nn][2], acc[mm][nn][3]);
        }
    }
}

// ---------------- persistent recurrent scan (HMMA step compute) ----------------
// Chain = 32 CTAs (bg). CTA: cols cg*32..+32 (M), batches bg*8..+8 (N=8).
// W_h fp16 hi/lo frags in REGISTERS (loaded once via gemm's proven ldmatrix
// A-pattern). h exchanged as a2 [hi|lo] rows; SMEM rows 0-7 = h-hi, 8-15 = h-lo
// so one ldsm.x4 (gemm's B-pattern) yields both B frags. 3-term MMA:
// Whi*hhi + Whi*hlo + Wlo*hhi (fp32-class accuracy).
__global__ __launch_bounds__(256,1) void scan_kernel(
    const __half* __restrict__ h0, const float* __restrict__ W_h,
    const float* __restrict__ pre, float* __restrict__ hout,
    __half* __restrict__ a2)
{
    __shared__ float red[8*32*8];          // [warp][m 0..31][n 0..7]
    const int tid = threadIdx.x, wid = tid >> 5, lane = tid & 31;
    const int bg = blockIdx.x >> 5, cg = blockIdx.x & 31;
    unsigned* bar = &g_bar4[bg*64];
    const int g = lane >> 3, r8 = lane & 7;
    __half* hsm = (__half*)dynsm;          // [32 rows][1032 halfs]

    // ---- init: W_h fp16 hi/lo frags (two passes over one 32-row region) ----
    unsigned wfh[2][8][4], wfl[2][8][4];
    #pragma unroll
    for (int pass = 0; pass < 2; pass++){
        for (int i = 0; i < 32; i++){
            int gi = tid + i*256;                 // float4 id, 0..8191
            int row = gi >> 8, c4 = (gi & 255) << 2;
            float4 v = *(const float4*)(W_h + (size_t)(cg*32 + row)*HDIM + c4);
            uint2 uh, ul; split4h(v, uh, ul);
            *(uint2*)((char*)hsm + row*WROWB + c4*2) = (pass == 0) ? uh : ul;
        }
        __syncthreads();
        #pragma unroll
        for (int mm = 0; mm < 2; mm++)
            #pragma unroll
            for (int kt = 0; kt < 8; kt++){
                int row = mm*16 + r8 + (g & 1)*8;
                unsigned addr = smem_u32((char*)hsm + row*WROWB
                                + wid*256 + kt*32 + (g >> 1)*16);
                if (pass == 0) ldsm4(wfh[mm][kt], addr);
                else           ldsm4(wfl[mm][kt], addr);
            }
        __syncthreads();
    }

    const int m_ = tid & 31, n_ = tid >> 5;   // reduce role: (out col, batch)
    const int gb = bg*8 + n_;
    const int oc = cg*32 + m_;

    for (int t = 0; t < SEQL; t++){
        const float preval = pre[((size_t)t*BATCH + gb)*HDIM + oc];

        // load h_{t-1} [hi|lo] rows into SMEM: hi -> rows 0-7, lo -> rows 8-15
        const __half* hbase; size_t rstride;
        if (t == 0){ hbase = h0 + (size_t)bg*8*K2; rstride = K2; }
        else { hbase = a2 + ((size_t)(bg*8)*SEQL + (t-1))*K2; rstride = (size_t)SEQL*K2; }
        #pragma unroll
        for (int i = 0; i < 8; i++){
            int s = tid + i*256;                  // 16B seg id 0..2047
            int j = s >> 8;                       // batch row 0..7
            int kk = (s & 255) << 3;              // half offset 0..2040
            uint4 v = *(const uint4*)(hbase + (size_t)j*rstride + kk);
            int drow = (kk < 1024) ? j : j + 8;
            *(uint4*)((char*)hsm + drow*WROWB + (kk & 1023)*2) = v;
        }
        __syncthreads();

        float c0[4] = {0,0,0,0}, c1[4] = {0,0,0,0};
        #pragma unroll
        for (int kt = 0; kt < 8; kt++){
            unsigned hf[4];
            int row = r8 + (g >> 1)*8;
            ldsm4(hf, smem_u32((char*)hsm + row*WROWB + wid*256 + kt*32 + (g & 1)*16));
            mma16816h(c0, wfh[0][kt], &hf[0]);    // Whi * hhi
            mma16816h(c0, wfh[0][kt], &hf[2]);    // Whi * hlo
            mma16816h(c0, wfl[0][kt], &hf[0]);    // Wlo * hhi
            mma16816h(c1, wfh[1][kt], &hf[0]);
            mma16816h(c1, wfh[1][kt], &hf[2]);
            mma16816h(c1, wfl[1][kt], &hf[0]);
        }

        {
            int row = lane >> 2, col = (lane & 3)*2;
            float* rw = red + wid*256;
            rw[(row     )*8 + col] = c0[0]; rw[(row     )*8 + col+1] = c0[1];
            rw[(row +  8)*8 + col] = c0[2]; rw[(row +  8)*8 + col+1] = c0[3];
            rw[(row + 16)*8 + col] = c1[0]; rw[(row + 16)*8 + col+1] = c1[1];
            rw[(row + 24)*8 + col] = c1[2]; rw[(row + 24)*8 + col+1] = c1[3];
        }
        __syncthreads();

        {
            float dot = 0.f;
            #pragma unroll
            for (int w = 0; w < 8; w++) dot += red[w*256 + m_*8 + n_];
            float hval = tanhf(dot + preval);
            if (t == SEQL-1) hout[((size_t)t*BATCH + gb)*HDIM + oc] = hval;
            __half hh = __float2half(hval);
            __half hl = __float2half(hval - __half2float(hh));
            size_t arow = ((size_t)gb*SEQL + t)*K2;
            a2[arow + oc]        = hh;
            a2[arow + 1024 + oc] = hl;
        }

        if (t + 1 < SEQL){
            __syncthreads();
            if (tid == 0){
                bar_arrive_release(bar);
                const unsigned target = 32u*(unsigned)(t+1);
                if (ld_acquire_gpu(bar) < target){
                    while (ld_acquire_gpu(bar) < target) __nanosleep(64);
                }
            }
            __syncthreads();
        }
    }
}

__global__ void copy_hidden(float* __restrict__ dst){
    int i = blockIdx.x * blockDim.x + threadIdx.x;
    dst[i] = g_hout[(size_t)(511*32)*HDIM + i];
}

extern "C" void kernel_launch(void* const* d_in, const int* in_sizes, int n_in,
                              void* d_out, int out_size) {
    const void*  x      = d_in[0];
    const float* hidden = (const float*)d_in[1];
    const float* emb    = (const float*)d_in[2];
    const float* W_h    = (const float*)d_in[3];
    const float* W_e    = (const float*)d_in[4];
    const float* W_o    = (const float*)d_in[5];
    float* out = (float*)d_out;

    float *pre, *hout; int *map1; __half *a2, *bo, *be, *h0;
    cudaGetSymbolAddress((void**)&pre,  g_pre);
    cudaGetSymbolAddress((void**)&hout, g_hout);
    cudaGetSymbolAddress((void**)&map1, g_map1);
    cudaGetSymbolAddress((void**)&a2,   g_a2);
    cudaGetSymbolAddress((void**)&bo,   g_bo);
    cudaGetSymbolAddress((void**)&be,   g_be);
    cudaGetSymbolAddress((void**)&h0,   g_h0);

    cudaFuncSetAttribute(gemm_tc, cudaFuncAttributeMaxDynamicSharedMemorySize,
                         NSTAGE*STAGE_BYTES);
    cudaFuncSetAttribute(scan_kernel, cudaFuncAttributeMaxDynamicSharedMemorySize,
                         SCAN_SMEM);

    detect_kernel<<<1, 32>>>((const long long*)x);
    build_maps<<<64, 256>>>(x);

    // Phase 1: pre = emb[x] @ W_e^T via fp16 HMMA (A = gathered [Ah|Al])
    convB_kernel<<<HDIM, 256>>>(W_e, be);
    convA_kernel<<<ML, 256>>>(emb, a2, map1);
    gemm_tc<<<dim3(8, 64), 512, NSTAGE*STAGE_BYTES>>>(a2, be, pre, HDIM);

    // independent preps before the scan
    convB_kernel<<<VOCAB, 256>>>(W_o, bo);
    convH0_kernel<<<32, 256>>>(hidden, h0);

    // Phase 2: persistent HMMA scan; emits fp16 split-A for phase 3 directly
    scan_kernel<<<128, 256, SCAN_SMEM>>>(h0, W_h, pre, hout, a2);

    // Phase 3: logits = outputs @ W_o^T via fp16 HMMA
    gemm_tc<<<dim3(64, 64), 512, NSTAGE*STAGE_BYTES>>>(a2, bo, out, VOCAB);

    if (out_size >= LOGITS_ELEMS + BATCH*HDIM)
        copy_hidden<<<32, 1024>>>(out + LOGITS_ELEMS);
}

// round 12
// speedup vs baseline: 2.9553x; 1.0099x over previous
#include <cuda_runtime.h>
#include <cuda_bf16.h>
#include <cuda_fp16.h>
#include <cstdint>

typedef unsigned long long u64;

#define SEQL   512
#define BATCH  32
#define HDIM   1024
#define VOCAB  8192
#define ML     (BATCH*SEQL)              /* 16384 */
#define LOGITS_ELEMS 134217728           /* 32*512*8192 */
#define K2     2048                      /* fp16 A-split: [Ah|Al] x [Bh wrap] */
#define BK     64
#define KCH    32                        /* K2 / BK */
#define STAGE_BYTES 49152                /* (256+128)*64*2 */
#define NSTAGE 3
#define WSTRIDE 1032                     /* scan smem row: 1024 halfs + 8 pad */
#define WROWB   2064                     /* bytes per scan smem row */
#define SCAN_SMEM 66048                  /* 32 rows * 2064 B */

// ---------------- scratch (cudaMalloc forbidden) ----------------
__device__ float g_pre[ML*HDIM];                 // 64 MB, [t][b][h]
__device__ float g_hout[ML*HDIM];                // 64 MB, [t][b][h] (only t=511 used)
__device__ __half g_a2[(size_t)ML*K2];           // 64 MB: fp16 [Ah|Al] rows
__device__ __half g_bo[(size_t)VOCAB*HDIM];      // 16 MB: fp16 W_o (hi only)
__device__ __half g_be[(size_t)HDIM*HDIM];       //  2 MB: fp16 W_e (hi only)
__device__ __half g_h0[BATCH*K2];                // 128 KB: initial hidden [hi|lo]
__device__ int   g_map1[ML];             // row m=t*32+b -> embedding id
__device__ int   g_is64;
__device__ unsigned g_bar4[4*64];        // per-batch-group barrier counters

// ---------------- barrier primitives ----------------
__device__ __forceinline__ void bar_arrive_release(unsigned* p){
    asm volatile("red.release.gpu.global.add.u32 [%0], 1;" :: "l"(p) : "memory");
}
__device__ __forceinline__ unsigned ld_acquire_gpu(const unsigned* p){
    unsigned v;
    asm volatile("ld.acquire.gpu.global.u32 %0, [%1];" : "=r"(v) : "l"(p) : "memory");
    return v;
}

// ---------------- sm80-class tensor primitives (valid on plain sm_103) ----------------
__device__ __forceinline__ unsigned smem_u32(const void* p){
    unsigned a;
    asm("{ .reg .u64 t; cvta.to.shared.u64 t, %1; cvt.u32.u64 %0, t; }" : "=r"(a) : "l"(p));
    return a;
}
__device__ __forceinline__ void ldsm4(unsigned* r, unsigned addr){
    asm volatile("ldmatrix.sync.aligned.m8n8.x4.shared.b16 {%0,%1,%2,%3}, [%4];"
        : "=r"(r[0]), "=r"(r[1]), "=r"(r[2]), "=r"(r[3]) : "r"(addr));
}
__device__ __forceinline__ void mma16816h(float* d, const unsigned* a, const unsigned* b){
    asm volatile(
        "mma.sync.aligned.m16n8k16.row.col.f32.f16.f16.f32 "
        "{%0,%1,%2,%3}, {%4,%5,%6,%7}, {%8,%9}, {%0,%1,%2,%3};"
        : "+f"(d[0]), "+f"(d[1]), "+f"(d[2]), "+f"(d[3])
        : "r"(a[0]), "r"(a[1]), "r"(a[2]), "r"(a[3]), "r"(b[0]), "r"(b[1]));
}
__device__ __forceinline__ void cpasync16(unsigned saddr, const void* g){
    asm volatile("cp.async.cg.shared.global [%0], [%1], 16;" :: "r"(saddr), "l"(g) : "memory");
}
__device__ __forceinline__ void cp_commit(){
    asm volatile("cp.async.commit_group;" ::: "memory");
}
template<int N>
__device__ __forceinline__ void cp_wait(){
    asm volatile("cp.async.wait_group %0;" :: "n"(N) : "memory");
}

// ---------------- id dtype detection / maps ----------------
__global__ void detect_kernel(const long long* __restrict__ x){
    if (threadIdx.x == 0 && blockIdx.x == 0){
        int ok = 1;
        #pragma unroll
        for (int i = 0; i < 16; i++){
            long long v = x[i];
            if (v < 0 || v >= VOCAB) ok = 0;
        }
        g_is64 = ok;
    }
}

__global__ void build_maps(const void* __restrict__ xraw){
    int i = blockIdx.x * blockDim.x + threadIdx.x;
    if (i < 4*64) g_bar4[i] = 0u;
    if (i >= ML) return;
    int is64 = g_is64;
    int t = i >> 5, b = i & 31;
    long long id = is64 ? ((const long long*)xraw)[b*SEQL + t]
                        : (long long)((const int*)xraw)[b*SEQL + t];
    g_map1[i] = (int)id;
}

// ---------------- fp32 -> fp16 conversions ----------------
__device__ __forceinline__ void split4h(float4 v, uint2& uh, uint2& ul){
    __half h0 = __float2half(v.x), h1 = __float2half(v.y);
    __half h2 = __float2half(v.z), h3 = __float2half(v.w);
    __half l0 = __float2half(v.x - __half2float(h0));
    __half l1 = __float2half(v.y - __half2float(h1));
    __half l2 = __float2half(v.z - __half2float(h2));
    __half l3 = __float2half(v.w - __half2float(h3));
    __half2 p0(h0, h1), p1(h2, h3), q0(l0, l1), q1(l2, l3);
    uh.x = *(unsigned*)&p0; uh.y = *(unsigned*)&p1;
    ul.x = *(unsigned*)&q0; ul.y = *(unsigned*)&q1;
}
// A rows (K2): [Ah | Al], gathered via map.
__global__ void convA_kernel(const float* __restrict__ src, __half* __restrict__ dst,
                             const int* __restrict__ map){
    int i = blockIdx.x * blockDim.x + threadIdx.x;   // over ML*256
    int r = i >> 8, k4 = (i & 255) << 2;
    float4 v = *(const float4*)(src + (size_t)map[r]*HDIM + k4);
    uint2 uh, ul; split4h(v, uh, ul);
    size_t base = (size_t)r * K2;
    *(uint2*)(dst + base + k4)        = uh;
    *(uint2*)(dst + base + 1024 + k4) = ul;
}
// B: plain fp16 downcast (hi only; GEMM re-reads the same copy for both halves).
__global__ void convB_kernel(const float* __restrict__ src, __half* __restrict__ dst){
    int i = blockIdx.x * blockDim.x + threadIdx.x;   // over rows*256
    int r = i >> 8, k4 = (i & 255) << 2;
    float4 v = *(const float4*)(src + (size_t)r*HDIM + k4);
    __half2 p0(__float2half(v.x), __float2half(v.y));
    __half2 p1(__float2half(v.z), __float2half(v.w));
    uint2 uh; uh.x = *(unsigned*)&p0; uh.y = *(unsigned*)&p1;
    *(uint2*)(dst + (size_t)r*HDIM + k4) = uh;
}
// initial hidden -> [hi|lo] fp16 rows (same format as a2 rows)
__global__ void convH0_kernel(const float* __restrict__ hidden, __half* __restrict__ h0){
    int i = blockIdx.x * blockDim.x + threadIdx.x;   // 32*256
    int b = i >> 8, k4 = (i & 255) << 2;
    float4 v = *(const float4*)(hidden + (size_t)b*HDIM + k4);
    uint2 uh, ul; split4h(v, uh, ul);
    *(uint2*)(h0 + (size_t)b*K2 + k4)        = uh;
    *(uint2*)(h0 + (size_t)b*K2 + 1024 + k4) = ul;
}

// ---------------- fp16 NT GEMM via mma.sync (HMMA) ----------------
__device__ __forceinline__ unsigned sw_off(int row, int seg){
    return (unsigned)(row*128 + ((seg ^ (row & 7)) << 4));
}

extern __shared__ __align__(16) char dynsm[];
__global__ __launch_bounds__(512,1) void gemm_tc(
    const __half* __restrict__ A, const __half* __restrict__ B,
    float* __restrict__ C, int ldc)
{
    const int tid = threadIdx.x, wid = tid >> 5, lane = tid & 31;
    const int bn = blockIdx.x, bm = blockIdx.y;
    const unsigned sbase = smem_u32(dynsm);

    const __half* Abase = A + (size_t)(bm*256)*K2;
    const __half* Bbase = B + (size_t)(bn*128)*HDIM;

    auto issue_stage = [&](int c, int s){
        const unsigned so = sbase + (unsigned)s*STAGE_BYTES;
        const int ak = c*BK;
        const int bk = (c & 15)*BK;
        #pragma unroll
        for (int i = 0; i < 6; i++){
            int idx = tid + i*512;
            int row = idx >> 3, seg = idx & 7;
            if (row < 256){
                cpasync16(so + sw_off(row, seg),
                          Abase + (size_t)row*K2 + ak + seg*8);
            } else {
                int r = row - 256;
                cpasync16(so + 32768u + sw_off(r, seg),
                          Bbase + (size_t)r*HDIM + bk + seg*8);
            }
        }
        cp_commit();
    };

    const int wm = (wid >> 1)*32;
    const int wn = (wid & 1)*64;
    const int g = lane >> 3, r8 = lane & 7;

    float acc[2][8][4];
    #pragma unroll
    for (int mm = 0; mm < 2; mm++)
        #pragma unroll
        for (int nn = 0; nn < 8; nn++)
            #pragma unroll
            for (int j = 0; j < 4; j++) acc[mm][nn][j] = 0.f;

    issue_stage(0, 0);
    issue_stage(1, 1);

    int s = 0;
    for (int c = 0; c < KCH; c++){
        cp_wait<1>();
        __syncthreads();
        if (c + 2 < KCH) issue_stage(c + 2, (c + 2) % NSTAGE);

        const unsigned offA = sbase + (unsigned)s*STAGE_BYTES;
        const unsigned offB = offA + 32768u;
        #pragma unroll
        for (int ks = 0; ks < 4; ks++){
            unsigned af[2][4], bf[4][4];
            #pragma unroll
            for (int mm = 0; mm < 2; mm++){
                int row = wm + mm*16 + r8 + (g & 1)*8;
                ldsm4(af[mm], offA + sw_off(row, ks*2 + (g >> 1)));
            }
            #pragma unroll
            for (int nt = 0; nt < 4; nt++){
                int row = wn + nt*16 + r8 + (g >> 1)*8;
                ldsm4(bf[nt], offB + sw_off(row, ks*2 + (g & 1)));
            }
            #pragma unroll
            for (int mm = 0; mm < 2; mm++)
                #pragma unroll
                for (int nt = 0; nt < 4; nt++){
                    mma16816h(acc[mm][2*nt],   af[mm], &bf[nt][0]);
                    mma16816h(acc[mm][2*nt+1], af[mm], &bf[nt][2]);
                }
        }
        s = (s + 1 == NSTAGE) ? 0 : s + 1;
    }

    const int erow = lane >> 2, ecol = (lane & 3)*2;
    #pragma unroll
    for (int mm = 0; mm < 2; mm++){
        #pragma unroll
        for (int nn = 0; nn < 8; nn++){
            size_t row = (size_t)(bm*256 + wm + mm*16 + erow);
            size_t col = (size_t)(bn*128 + wn + nn*8 + ecol);
            *(float2*)&C[row*ldc + col]       = make_float2(acc[mm][nn][0], acc[mm][nn][1]);
            *(float2*)&C[(row + 8)*ldc + col] = make_float2(acc[mm][nn][2], acc[mm][nn][3]);
        }
    }
}

// ---------------- persistent recurrent scan (HMMA step compute) ----------------
// Chain = 32 CTAs (bg). CTA: cols cg*32..+32 (M), batches bg*8..+8 (N=8).
// W_h fp16 hi/lo frags in REGISTERS (loaded once via gemm's proven ldmatrix
// A-pattern). h exchanged as a2 [hi|lo] rows; SMEM rows 0-7 = h-hi, 8-15 = h-lo
// so one ldsm.x4 (gemm's B-pattern) yields both B frags. 3-term MMA:
// Whi*hhi + Whi*hlo + Wlo*hhi (fp32-class accuracy).
__global__ __launch_bounds__(256,1) void scan_kernel(
    const __half* __restrict__ h0, const float* __restrict__ W_h,
    const float* __restrict__ pre, float* __restrict__ hout,
    __half* __restrict__ a2)
{
    __shared__ float red[8*32*8];          // [warp][m 0..31][n 0..7]
    const int tid = threadIdx.x, wid = tid >> 5, lane = tid & 31;
    const int bg = blockIdx.x >> 5, cg = blockIdx.x & 31;
    unsigned* bar = &g_bar4[bg*64];
    const int g = lane >> 3, r8 = lane & 7;
    __half* hsm = (__half*)dynsm;          // [32 rows][1032 halfs]

    // ---- init: W_h fp16 hi/lo frags (two passes over one 32-row region) ----
    unsigned wfh[2][8][4], wfl[2][8][4];
    #pragma unroll
    for (int pass = 0; pass < 2; pass++){
        for (int i = 0; i < 32; i++){
            int gi = tid + i*256;                 // float4 id, 0..8191
            int row = gi >> 8, c4 = (gi & 255) << 2;
            float4 v = *(const float4*)(W_h + (size_t)(cg*32 + row)*HDIM + c4);
            uint2 uh, ul; split4h(v, uh, ul);
            *(uint2*)((char*)hsm + row*WROWB + c4*2) = (pass == 0) ? uh : ul;
        }
        __syncthreads();
        #pragma unroll
        for (int mm = 0; mm < 2; mm++)
            #pragma unroll
            for (int kt = 0; kt < 8; kt++){
                int row = mm*16 + r8 + (g & 1)*8;
                unsigned addr = smem_u32((char*)hsm + row*WROWB
                                + wid*256 + kt*32 + (g >> 1)*16);
                if (pass == 0) ldsm4(wfh[mm][kt], addr);
                else           ldsm4(wfl[mm][kt], addr);
            }
        __syncthreads();
    }

    const int m_ = tid & 31, n_ = tid >> 5;   // reduce role: (out col, batch)
    const int gb = bg*8 + n_;
    const int oc = cg*32 + m_;

    for (int t = 0; t < SEQL; t++){
        const float preval = pre[((size_t)t*BATCH + gb)*HDIM + oc];

        // load h_{t-1} [hi|lo] rows into SMEM: hi -> rows 0-7, lo -> rows 8-15
        const __half* hbase; size_t rstride;
        if (t == 0){ hbase = h0 + (size_t)bg*8*K2; rstride = K2; }
        else { hbase = a2 + ((size_t)(bg*8)*SEQL + (t-1))*K2; rstride = (size_t)SEQL*K2; }
        #pragma unroll
        for (int i = 0; i < 8; i++){
            int s = tid + i*256;                  // 16B seg id 0..2047
            int j = s >> 8;                       // batch row 0..7
            int kk = (s & 255) << 3;              // half offset 0..2040
            uint4 v = *(const uint4*)(hbase + (size_t)j*rstride + kk);
            int drow = (kk < 1024) ? j : j + 8;
            *(uint4*)((char*)hsm + drow*WROWB + (kk & 1023)*2) = v;
        }
        __syncthreads();

        float c0[4] = {0,0,0,0}, c1[4] = {0,0,0,0};
        #pragma unroll
        for (int kt = 0; kt < 8; kt++){
            unsigned hf[4];
            int row = r8 + (g >> 1)*8;
            ldsm4(hf, smem_u32((char*)hsm + row*WROWB + wid*256 + kt*32 + (g & 1)*16));
            mma16816h(c0, wfh[0][kt], &hf[0]);    // Whi * hhi
            mma16816h(c0, wfh[0][kt], &hf[2]);    // Whi * hlo
            mma16816h(c0, wfl[0][kt], &hf[0]);    // Wlo * hhi
            mma16816h(c1, wfh[1][kt], &hf[0]);
            mma16816h(c1, wfh[1][kt], &hf[2]);
            mma16816h(c1, wfl[1][kt], &hf[0]);
        }

        {
            int row = lane >> 2, col = (lane & 3)*2;
            float* rw = red + wid*256;
            rw[(row     )*8 + col] = c0[0]; rw[(row     )*8 + col+1] = c0[1];
            rw[(row +  8)*8 + col] = c0[2]; rw[(row +  8)*8 + col+1] = c0[3];
            rw[(row + 16)*8 + col] = c1[0]; rw[(row + 16)*8 + col+1] = c1[1];
            rw[(row + 24)*8 + col] = c1[2]; rw[(row + 24)*8 + col+1] = c1[3];
        }
        __syncthreads();

        {
            float dot = 0.f;
            #pragma unroll
            for (int w = 0; w < 8; w++) dot += red[w*256 + m_*8 + n_];
            float hval = tanhf(dot + preval);
            if (t == SEQL-1) hout[((size_t)t*BATCH + gb)*HDIM + oc] = hval;
            __half hh = __float2half(hval);
            __half hl = __float2half(hval - __half2float(hh));
            size_t arow = ((size_t)gb*SEQL + t)*K2;
            a2[arow + oc]        = hh;
            a2[arow + 1024 + oc] = hl;
        }

        if (t + 1 < SEQL){
            __syncthreads();
            if (tid == 0){
                bar_arrive_release(bar);
                const unsigned target = 32u*(unsigned)(t+1);
                if (ld_acquire_gpu(bar) < target){
                    while (ld_acquire_gpu(bar) < target) __nanosleep(64);
                }
            }
            __syncthreads();
        }
    }
}

__global__ void copy_hidden(float* __restrict__ dst){
    int i = blockIdx.x * blockDim.x + threadIdx.x;
    dst[i] = g_hout[(size_t)(511*32)*HDIM + i];
}

extern "C" void kernel_launch(void* const* d_in, const int* in_sizes, int n_in,
                              void* d_out, int out_size) {
    const void*  x      = d_in[0];
    const float* hidden = (const float*)d_in[1];
    const float* emb    = (const float*)d_in[2];
    const float* W_h    = (const float*)d_in[3];
    const float* W_e    = (const float*)d_in[4];
    const float* W_o    = (const float*)d_in[5];
    float* out = (float*)d_out;

    float *pre, *hout; int *map1; __half *a2, *bo, *be, *h0;
    cudaGetSymbolAddress((void**)&pre,  g_pre);
    cudaGetSymbolAddress((void**)&hout, g_hout);
    cudaGetSymbolAddress((void**)&map1, g_map1);
    cudaGetSymbolAddress((void**)&a2,   g_a2);
    cudaGetSymbolAddress((void**)&bo,   g_bo);
    cudaGetSymbolAddress((void**)&be,   g_be);
    cudaGetSymbolAddress((void**)&h0,   g_h0);

    cudaFuncSetAttribute(gemm_tc, cudaFuncAttributeMaxDynamicSharedMemorySize,
                         NSTAGE*STAGE_BYTES);
    cudaFuncSetAttribute(scan_kernel, cudaFuncAttributeMaxDynamicSharedMemorySize,
                         SCAN_SMEM);

    detect_kernel<<<1, 32>>>((const long long*)x);
    build_maps<<<64, 256>>>(x);

    // Phase 1: pre = emb[x] @ W_e^T via fp16 HMMA (A = gathered [Ah|Al])
    convB_kernel<<<HDIM, 256>>>(W_e, be);
    convA_kernel<<<ML, 256>>>(emb, a2, map1);
    gemm_tc<<<dim3(8, 64), 512, NSTAGE*STAGE_BYTES>>>(a2, be, pre, HDIM);

    // independent preps before the scan
    convB_kernel<<<VOCAB, 256>>>(W_o, bo);
    convH0_kernel<<<32, 256>>>(hidden, h0);

    // Phase 2: persistent HMMA scan; emits fp16 split-A for phase 3 directly
    scan_kernel<<<128, 256, SCAN_SMEM>>>(h0, W_h, pre, hout, a2);

    // Phase 3: logits = outputs @ W_o^T via fp16 HMMA
    gemm_tc<<<dim3(64, 64), 512, NSTAGE*STAGE_BYTES>>>(a2, bo, out, VOCAB);

    if (out_size >= LOGITS_ELEMS + BATCH*HDIM)
        copy_hidden<<<32, 1024>>>(out + LOGITS_ELEMS);
}